// round 4
// baseline (speedup 1.0000x reference)
#include <cuda_runtime.h>
#include <cuda_bf16.h>
#include <stdint.h>
#include <math.h>

#define Bb 8
#define Nn 2048
#define Dd 512
#define Pp 16
#define PH 512
#define ROWS (Bb*Nn)   // 16384

// ---------------- scratch ---------------------------------------------------
__device__ __nv_bfloat16 g_ctx_h[(size_t)ROWS * Dd];
__device__ __nv_bfloat16 g_ctx_l[(size_t)ROWS * Dd];
__device__ __nv_bfloat16 g_W_h[(size_t)PH * Dd];
__device__ __nv_bfloat16 g_W_l[(size_t)PH * Dd];
__device__ __nv_bfloat16 g_G_h[(size_t)ROWS * PH];
__device__ __nv_bfloat16 g_G_l[(size_t)ROWS * PH];
__device__ float g_rmax[ROWS];
__device__ float g_rinv[ROWS];

// ---------------- small PTX helpers (base-ISA only; no 'a' features) --------
__device__ __forceinline__ uint32_t smem_u32(const void* p) {
    uint32_t a;
    asm("{ .reg .u64 t; cvta.to.shared.u64 t, %1; cvt.u32.u64 %0, t; }" : "=r"(a) : "l"(p));
    return a;
}
__device__ __forceinline__ void cpa16(uint32_t saddr, const void* g) {
    asm volatile("cp.async.cg.shared.global [%0], [%1], 16;" :: "r"(saddr), "l"(g));
}
#define CP_COMMIT() asm volatile("cp.async.commit_group;" ::: "memory")
#define CP_WAIT(n)  asm volatile("cp.async.wait_group %0;" :: "n"(n) : "memory")

__device__ __forceinline__ void ldsm4(uint32_t& d0, uint32_t& d1, uint32_t& d2, uint32_t& d3,
                                      uint32_t addr) {
    asm volatile("ldmatrix.sync.aligned.m8n8.x4.shared.b16 {%0,%1,%2,%3}, [%4];"
                 : "=r"(d0), "=r"(d1), "=r"(d2), "=r"(d3) : "r"(addr));
}
__device__ __forceinline__ void mma_bf16(float* c, const uint32_t* a, uint32_t b0, uint32_t b1) {
    asm volatile("mma.sync.aligned.m16n8k16.row.col.f32.bf16.bf16.f32 "
                 "{%0,%1,%2,%3}, {%4,%5,%6,%7}, {%8,%9}, {%0,%1,%2,%3};"
                 : "+f"(c[0]), "+f"(c[1]), "+f"(c[2]), "+f"(c[3])
                 : "r"(a[0]), "r"(a[1]), "r"(a[2]), "r"(a[3]), "r"(b0), "r"(b1));
}

// ---------------- split fp32 -> (hi, lo) bf16 ------------------------------
__global__ __launch_bounds__(256)
void split_kernel(const float* __restrict__ x, __nv_bfloat16* __restrict__ h,
                  __nv_bfloat16* __restrict__ l, int n4)
{
    int i = blockIdx.x * blockDim.x + threadIdx.x;
    if (i >= n4) return;
    float4 v = ((const float4*)x)[i];
    __nv_bfloat16 h0 = __float2bfloat16(v.x), h1 = __float2bfloat16(v.y);
    __nv_bfloat16 h2 = __float2bfloat16(v.z), h3 = __float2bfloat16(v.w);
    __nv_bfloat16 l0 = __float2bfloat16(v.x - __bfloat162float(h0));
    __nv_bfloat16 l1 = __float2bfloat16(v.y - __bfloat162float(h1));
    __nv_bfloat16 l2 = __float2bfloat16(v.z - __bfloat162float(h2));
    __nv_bfloat16 l3 = __float2bfloat16(v.w - __bfloat162float(h3));
    __nv_bfloat162 hp0 = __halves2bfloat162(h0, h1), hp1 = __halves2bfloat162(h2, h3);
    __nv_bfloat162 lp0 = __halves2bfloat162(l0, l1), lp1 = __halves2bfloat162(l2, l3);
    uint2 hv, lv;
    hv.x = *(uint32_t*)&hp0; hv.y = *(uint32_t*)&hp1;
    lv.x = *(uint32_t*)&lp0; lv.y = *(uint32_t*)&lp1;
    ((uint2*)h)[i] = hv;
    ((uint2*)l)[i] = lv;
}

// ---------------- mma.sync GEMM: C = f(alpha * A·B^T), 2-term bf16 split ---
// CTA tile 128x128, BK=32, 3-stage cp.async pipeline.
// 3 accumulation passes: Ahi·Bhi^T + Ahi·Blo^T + Alo·Bhi^T.
// EPI=0: store fp32 * alpha. EPI=1: relu, split into (Ch, Cl) bf16.
// SYM=1: blockIdx.x in [0,136) decodes to upper-triangular (bi<=bj) 128-block.
#define LDS_ROW 40          // 32 bf16 + 8 pad
#define ROWB    80
#define NIT     48          // 3 terms * (512/32)
#define BUF_B   10240       // 128*LDS_ROW*2 bytes
#define GEMM_SMEM (6*BUF_B) // 3 stages * (A+B)

template<int EPI, int SYM>
__global__ __launch_bounds__(256, 2)
void mma_gemm(const __nv_bfloat16* __restrict__ Ah, const __nv_bfloat16* __restrict__ Al,
              const __nv_bfloat16* __restrict__ Bh, const __nv_bfloat16* __restrict__ Bl,
              float* __restrict__ Cf, __nv_bfloat16* __restrict__ Ch, __nv_bfloat16* __restrict__ Cl,
              int Ncols, size_t sA, size_t sB, size_t sC, float alpha)
{
    extern __shared__ char dsm[];

    const int tid  = threadIdx.x;
    const int wid  = tid >> 5;
    const int lane = tid & 31;
    const int wm   = wid >> 2;        // 0..1  (M warp row, 64 rows)
    const int wn   = wid & 3;         // 0..3  (N warp col, 32 cols)

    int m0, n0;
    if (SYM) {
        int idx = blockIdx.x, bi = 0, bj = 0, off = 0;
#pragma unroll 1
        for (int i = 0; i < 16; i++) {
            int cnt = 16 - i;
            if (idx < off + cnt) { bi = i; bj = i + idx - off; break; }
            off += cnt;
        }
        m0 = bi * 128; n0 = bj * 128;
    } else {
        m0 = blockIdx.y * 128; n0 = blockIdx.x * 128;
    }

    const size_t zAb = (size_t)blockIdx.z * sA * 2;   // bytes
    const size_t zBb = (size_t)blockIdx.z * sB * 2;
    const size_t zC  = (size_t)blockIdx.z * sC;

    // load geometry: 512 16B-chunks per 128x32 tile; this thread does 2 (A) + 2 (B)
    const int r0 = tid >> 2;
    const int c0 = tid & 3;
    const uint32_t s_off0 = (uint32_t)r0 * ROWB + (uint32_t)c0 * 16;
    const size_t   a_off0 = (size_t)(m0 + r0) * 1024 + (size_t)c0 * 16;
    const size_t   b_off0 = (size_t)(n0 + r0) * 1024 + (size_t)c0 * 16;

    uint32_t as_b[3], bs_b[3];
#pragma unroll
    for (int s = 0; s < 3; s++) {
        as_b[s] = smem_u32(dsm + s * BUF_B);
        bs_b[s] = smem_u32(dsm + 3 * BUF_B + s * BUF_B);
    }

    const char* Ahb = (const char*)Ah + zAb;
    const char* Alb = (const char*)Al + zAb;
    const char* Bhb = (const char*)Bh + zBb;
    const char* Blb = (const char*)Bl + zBb;

    float acc[4][4][4];
#pragma unroll
    for (int i = 0; i < 4; i++)
#pragma unroll
        for (int j = 0; j < 4; j++)
#pragma unroll
            for (int k = 0; k < 4; k++) acc[i][j][k] = 0.f;

    const int rA = wm * 64 + (lane & 15);
    const int rB = wn * 32 + (lane & 15);
    const uint32_t half16 = (uint32_t)(lane >> 4) * 16;

    auto prefetch = [&](int it, int buf) {
        const int term = it >> 4;             // 0,1,2
        const int kc   = it & 15;
        const char* Ab  = (term == 2) ? Alb : Ahb;
        const char* Bbp = (term == 1) ? Blb : Bhb;
        const size_t koff = (size_t)kc * 64;
        uint32_t sa = as_b[buf] + s_off0;
        uint32_t sb = bs_b[buf] + s_off0;
        cpa16(sa,             Ab  + a_off0 + koff);
        cpa16(sa + 64 * ROWB, Ab  + a_off0 + (size_t)64 * 1024 + koff);
        cpa16(sb,             Bbp + b_off0 + koff);
        cpa16(sb + 64 * ROWB, Bbp + b_off0 + (size_t)64 * 1024 + koff);
    };

    prefetch(0, 0); CP_COMMIT();
    prefetch(1, 1); CP_COMMIT();
    prefetch(2, 2); CP_COMMIT();

    int buf = 0;
    for (int it = 0; it < NIT; ++it) {
        if (it < NIT - 3) { CP_WAIT(2); } else { CP_WAIT(0); }
        __syncthreads();

#pragma unroll
        for (int ks = 0; ks < 2; ks++) {
            uint32_t a[4][4];
            uint32_t b[2][4];
#pragma unroll
            for (int mi = 0; mi < 4; mi++) {
                uint32_t addr = as_b[buf] + (uint32_t)(rA + mi * 16) * ROWB
                              + (uint32_t)ks * 32 + half16;
                ldsm4(a[mi][0], a[mi][1], a[mi][2], a[mi][3], addr);
            }
#pragma unroll
            for (int nb = 0; nb < 2; nb++) {
                uint32_t addr = bs_b[buf] + (uint32_t)(rB + nb * 16) * ROWB
                              + (uint32_t)ks * 32 + half16;
                ldsm4(b[nb][0], b[nb][1], b[nb][2], b[nb][3], addr);
            }
#pragma unroll
            for (int mi = 0; mi < 4; mi++)
#pragma unroll
                for (int g = 0; g < 4; g++)
                    mma_bf16(acc[mi][g], a[mi], b[g >> 1][g & 1], b[g >> 1][(g & 1) + 2]);
        }
        __syncthreads();
        if (it + 3 < NIT) { prefetch(it + 3, buf); CP_COMMIT(); }
        buf = (buf == 2) ? 0 : buf + 1;
    }

    // ---------------- epilogue ----------------
    const int er = m0 + wm * 64 + (lane >> 2);
    const int ec = n0 + wn * 32 + (lane & 3) * 2;
#pragma unroll
    for (int mi = 0; mi < 4; mi++) {
#pragma unroll
        for (int g = 0; g < 4; g++) {
            const int r = er + mi * 16;
            const int c = ec + g * 8;
            if (EPI == 0) {
                float2 v0 = make_float2(acc[mi][g][0] * alpha, acc[mi][g][1] * alpha);
                float2 v1 = make_float2(acc[mi][g][2] * alpha, acc[mi][g][3] * alpha);
                *(float2*)(Cf + zC + (size_t)r * Ncols + c)       = v0;
                *(float2*)(Cf + zC + (size_t)(r + 8) * Ncols + c) = v1;
            } else {
#pragma unroll
                for (int hrow = 0; hrow < 2; hrow++) {
                    float v0 = fmaxf(acc[mi][g][2 * hrow + 0], 0.f);
                    float v1 = fmaxf(acc[mi][g][2 * hrow + 1], 0.f);
                    __nv_bfloat16 h0 = __float2bfloat16(v0), h1 = __float2bfloat16(v1);
                    __nv_bfloat16 l0 = __float2bfloat16(v0 - __bfloat162float(h0));
                    __nv_bfloat16 l1 = __float2bfloat16(v1 - __bfloat162float(h1));
                    __nv_bfloat162 hp = __halves2bfloat162(h0, h1);
                    __nv_bfloat162 lp = __halves2bfloat162(l0, l1);
                    const size_t o = (size_t)(r + 8 * hrow) * Ncols + c;
                    *(uint32_t*)(Ch + o) = *(uint32_t*)&hp;
                    *(uint32_t*)(Cl + o) = *(uint32_t*)&lp;
                }
            }
        }
    }
}

// ---------------- mirror: fill strictly-lower 128-blocks from upper --------
// grid.x = 120 pairs * 16 subtiles; grid.y = batch. 32x32 smem transpose.
__global__ __launch_bounds__(256)
void mirror_kernel(float* __restrict__ S)
{
    __shared__ float t[32][33];
    const int pair = blockIdx.x >> 4;
    const int sub  = blockIdx.x & 15;
    const int b    = blockIdx.y;

    int bi = 0, bj = 0, off = 0;
#pragma unroll 1
    for (int i = 0; i < 16; i++) {
        int cnt = 15 - i;
        if (pair < off + cnt) { bi = i; bj = i + 1 + pair - off; break; }
        off += cnt;
    }
    const int m0 = bi * 128 + (sub >> 2) * 32;   // source rows
    const int n0 = bj * 128 + (sub & 3) * 32;    // source cols
    const size_t base = (size_t)b * Nn * Nn;

    const int tx = threadIdx.x & 31;
    const int ty = threadIdx.x >> 5;             // 0..7
#pragma unroll
    for (int j = 0; j < 32; j += 8)
        t[ty + j][tx] = S[base + (size_t)(m0 + ty + j) * Nn + n0 + tx];
    __syncthreads();
#pragma unroll
    for (int j = 0; j < 32; j += 8)
        S[base + (size_t)(n0 + ty + j) * Nn + m0 + tx] = t[tx][ty + j];
}

// ---------------- softmax stats / normalize --------------------------------
__global__ __launch_bounds__(256)
void row_stats_kernel(const float* __restrict__ S)
{
    const int row = blockIdx.x;
    const int tid = threadIdx.x;
    const float4* p = (const float4*)(S + (size_t)row * Nn);
    float4 v1 = p[tid];
    float4 v2 = p[tid + 256];

    float mx = fmaxf(fmaxf(fmaxf(v1.x, v1.y), fmaxf(v1.z, v1.w)),
                     fmaxf(fmaxf(v2.x, v2.y), fmaxf(v2.z, v2.w)));
    __shared__ float red[8];
#pragma unroll
    for (int o = 16; o > 0; o >>= 1)
        mx = fmaxf(mx, __shfl_xor_sync(0xffffffffu, mx, o));
    if ((tid & 31) == 0) red[tid >> 5] = mx;
    __syncthreads();
    mx = red[0];
#pragma unroll
    for (int i = 1; i < 8; i++) mx = fmaxf(mx, red[i]);
    __syncthreads();

    float s = __expf(v1.x - mx) + __expf(v1.y - mx) + __expf(v1.z - mx) + __expf(v1.w - mx)
            + __expf(v2.x - mx) + __expf(v2.y - mx) + __expf(v2.z - mx) + __expf(v2.w - mx);
#pragma unroll
    for (int o = 16; o > 0; o >>= 1)
        s += __shfl_xor_sync(0xffffffffu, s, o);
    if ((tid & 31) == 0) red[tid >> 5] = s;
    __syncthreads();
    if (tid == 0) {
        float t = 0.f;
#pragma unroll
        for (int i = 0; i < 8; i++) t += red[i];
        g_rmax[row] = mx;
        g_rinv[row] = 1.f / t;
    }
}

__global__ __launch_bounds__(256)
void norm_mask_kernel(float* __restrict__ S, const int* __restrict__ mask)
{
    const int row = blockIdx.x;
    const int tid = threadIdx.x;
    const int b   = row >> 11;
    const float mn = (float)mask[row];

    const float4* rmax = (const float4*)(g_rmax + ((size_t)b << 11));
    const float4* rinv = (const float4*)(g_rinv + ((size_t)b << 11));
    const int4*   mrow = (const int4*)(mask + ((size_t)b << 11));
    float4* p = (float4*)(S + (size_t)row * Nn);

#pragma unroll
    for (int jj = 0; jj < 2; jj++) {
        const int j = tid + jj * 256;
        float4 v  = p[j];
        float4 mx = rmax[j];
        float4 iv = rinv[j];
        int4   mm = mrow[j];
        v.x = __expf(v.x - mx.x) * iv.x * mn * (float)mm.x;
        v.y = __expf(v.y - mx.y) * iv.y * mn * (float)mm.y;
        v.z = __expf(v.z - mx.z) * iv.z * mn * (float)mm.z;
        v.w = __expf(v.w - mx.w) * iv.w * mn * (float)mm.w;
        p[j] = v;
    }
}

// ---------------- launch ---------------------------------------------------
extern "C" void kernel_launch(void* const* d_in, const int* in_sizes, int n_in,
                              void* d_out, int out_size)
{
    const float* ctx  = (const float*)d_in[0];   // [8, 2048, 512]
    const float* W    = (const float*)d_in[1];   // [16, 32, 512]
    const int*   mask = (const int*)d_in[2];     // [8, 2048]
    float* out = (float*)d_out;                  // [8, 2048, 2048]

    void *p_ch, *p_cl, *p_wh, *p_wl, *p_gh, *p_gl;
    cudaGetSymbolAddress(&p_ch, g_ctx_h); cudaGetSymbolAddress(&p_cl, g_ctx_l);
    cudaGetSymbolAddress(&p_wh, g_W_h);   cudaGetSymbolAddress(&p_wl, g_W_l);
    cudaGetSymbolAddress(&p_gh, g_G_h);   cudaGetSymbolAddress(&p_gl, g_G_l);
    __nv_bfloat16* Ch = (__nv_bfloat16*)p_ch; __nv_bfloat16* Cl = (__nv_bfloat16*)p_cl;
    __nv_bfloat16* Wh = (__nv_bfloat16*)p_wh; __nv_bfloat16* Wl = (__nv_bfloat16*)p_wl;
    __nv_bfloat16* Gh = (__nv_bfloat16*)p_gh; __nv_bfloat16* Gl = (__nv_bfloat16*)p_gl;

    cudaFuncSetAttribute(mma_gemm<0,1>, cudaFuncAttributeMaxDynamicSharedMemorySize, GEMM_SMEM);
    cudaFuncSetAttribute(mma_gemm<1,0>, cudaFuncAttributeMaxDynamicSharedMemorySize, GEMM_SMEM);

    // K0: split inputs into hi/lo bf16
    {
        int n4 = ROWS * Dd / 4;
        split_kernel<<<(n4 + 255) / 256, 256>>>(ctx, Ch, Cl, n4);
        int w4 = PH * Dd / 4;
        split_kernel<<<(w4 + 255) / 256, 256>>>(W, Wh, Wl, w4);
    }
    // K1: G = relu(ctx @ W^T) -> Gh/Gl bf16 split (fused epilogue)
    {
        dim3 grid(PH / 128, ROWS / 128, 1);
        mma_gemm<1,0><<<grid, 256, GEMM_SMEM>>>(Ch, Cl, Wh, Wl, nullptr, Gh, Gl,
                                                PH, 0, 0, 0, 1.0f);
    }
    // K2: S_b = G_b @ G_b^T / 16 -> d_out, upper-triangular blocks only
    {
        dim3 grid(136, 1, Bb);
        mma_gemm<0,1><<<grid, 256, GEMM_SMEM>>>(Gh, Gl, Gh, Gl, out, nullptr, nullptr,
                                                Nn, (size_t)Nn * PH, (size_t)Nn * PH,
                                                (size_t)Nn * Nn, 1.0f / (float)Pp);
    }
    // K2b: mirror upper -> lower
    {
        dim3 grid(120 * 16, Bb);
        mirror_kernel<<<grid, 256>>>(out);
    }
    // K3/K4: symmetric softmax (row stats == col stats) + mask
    row_stats_kernel<<<ROWS, 256>>>(out);
    norm_mask_kernel<<<ROWS, 256>>>(out, mask);
}

// round 6
// speedup vs baseline: 1.5454x; 1.5454x over previous
#include <cuda_runtime.h>
#include <cuda_bf16.h>
#include <stdint.h>
#include <math.h>

#define Bb 8
#define Nn 2048
#define Dd 512
#define Pp 16
#define PH 512
#define ROWS (Bb*Nn)   // 16384

// ---------------- scratch ---------------------------------------------------
__device__ __nv_bfloat16 g_ctx_h[(size_t)ROWS * Dd];
__device__ __nv_bfloat16 g_ctx_l[(size_t)ROWS * Dd];
__device__ __nv_bfloat16 g_W_h[(size_t)PH * Dd];
__device__ __nv_bfloat16 g_W_l[(size_t)PH * Dd];
__device__ __nv_bfloat16 g_G_h[(size_t)ROWS * PH];
__device__ __nv_bfloat16 g_G_l[(size_t)ROWS * PH];
__device__ float g_rmax[ROWS];
__device__ float g_rinv[ROWS];

// ---------------- small PTX helpers (base-ISA only) ------------------------
__device__ __forceinline__ uint32_t smem_u32(const void* p) {
    uint32_t a;
    asm("{ .reg .u64 t; cvta.to.shared.u64 t, %1; cvt.u32.u64 %0, t; }" : "=r"(a) : "l"(p));
    return a;
}
__device__ __forceinline__ void cpa16(uint32_t saddr, const void* g) {
    asm volatile("cp.async.cg.shared.global [%0], [%1], 16;" :: "r"(saddr), "l"(g));
}
#define CP_COMMIT() asm volatile("cp.async.commit_group;" ::: "memory")
#define CP_WAIT(n)  asm volatile("cp.async.wait_group %0;" :: "n"(n) : "memory")

__device__ __forceinline__ void ldsm4(uint32_t& d0, uint32_t& d1, uint32_t& d2, uint32_t& d3,
                                      uint32_t addr) {
    asm volatile("ldmatrix.sync.aligned.m8n8.x4.shared.b16 {%0,%1,%2,%3}, [%4];"
                 : "=r"(d0), "=r"(d1), "=r"(d2), "=r"(d3) : "r"(addr));
}
__device__ __forceinline__ void mma_bf16(float* c, const uint32_t* a, uint32_t b0, uint32_t b1) {
    asm volatile("mma.sync.aligned.m16n8k16.row.col.f32.bf16.bf16.f32 "
                 "{%0,%1,%2,%3}, {%4,%5,%6,%7}, {%8,%9}, {%0,%1,%2,%3};"
                 : "+f"(c[0]), "+f"(c[1]), "+f"(c[2]), "+f"(c[3])
                 : "r"(a[0]), "r"(a[1]), "r"(a[2]), "r"(a[3]), "r"(b0), "r"(b1));
}

// ---------------- split fp32 -> (hi, lo) bf16 ------------------------------
__global__ __launch_bounds__(256)
void split_kernel(const float* __restrict__ x, __nv_bfloat16* __restrict__ h,
                  __nv_bfloat16* __restrict__ l, int n4)
{
    int i = blockIdx.x * blockDim.x + threadIdx.x;
    if (i >= n4) return;
    float4 v = ((const float4*)x)[i];
    __nv_bfloat16 h0 = __float2bfloat16(v.x), h1 = __float2bfloat16(v.y);
    __nv_bfloat16 h2 = __float2bfloat16(v.z), h3 = __float2bfloat16(v.w);
    __nv_bfloat16 l0 = __float2bfloat16(v.x - __bfloat162float(h0));
    __nv_bfloat16 l1 = __float2bfloat16(v.y - __bfloat162float(h1));
    __nv_bfloat16 l2 = __float2bfloat16(v.z - __bfloat162float(h2));
    __nv_bfloat16 l3 = __float2bfloat16(v.w - __bfloat162float(h3));
    __nv_bfloat162 hp0 = __halves2bfloat162(h0, h1), hp1 = __halves2bfloat162(h2, h3);
    __nv_bfloat162 lp0 = __halves2bfloat162(l0, l1), lp1 = __halves2bfloat162(l2, l3);
    uint2 hv, lv;
    hv.x = *(uint32_t*)&hp0; hv.y = *(uint32_t*)&hp1;
    lv.x = *(uint32_t*)&lp0; lv.y = *(uint32_t*)&lp1;
    ((uint2*)h)[i] = hv;
    ((uint2*)l)[i] = lv;
}

// ---------------- mma.sync GEMM (R3 2-stage mainloop) ----------------------
// C = f(alpha * A·B^T); 3 accumulation passes Ahi·Bhi^T + Ahi·Blo^T + Alo·Bhi^T.
// EPI=0: fp32 * alpha.  EPI=1: relu + split into (Ch, Cl).
// SYM=1: blockIdx.x in [0,136) -> upper-triangular (bi<=bj) 128-block.
#define LDS_ROW 40          // 32 bf16 + 8 pad = 80 bytes
#define ROWB    80
#define NIT     48          // 3 terms * (512/32)

template<int EPI, int SYM>
__global__ __launch_bounds__(256, 2)
void mma_gemm(const __nv_bfloat16* __restrict__ Ah, const __nv_bfloat16* __restrict__ Al,
              const __nv_bfloat16* __restrict__ Bh, const __nv_bfloat16* __restrict__ Bl,
              float* __restrict__ Cf, __nv_bfloat16* __restrict__ Ch, __nv_bfloat16* __restrict__ Cl,
              int Ncols, size_t sA, size_t sB, size_t sC, float alpha)
{
    __shared__ __align__(16) __nv_bfloat16 As[2][128 * LDS_ROW];
    __shared__ __align__(16) __nv_bfloat16 Bs[2][128 * LDS_ROW];

    const int tid  = threadIdx.x;
    const int wid  = tid >> 5;
    const int lane = tid & 31;
    const int wm   = wid >> 2;        // 0..1  (M warp row, 64 rows)
    const int wn   = wid & 3;         // 0..3  (N warp col, 32 cols)

    int m0, n0;
    if (SYM) {
        int idx = blockIdx.x, bi = 0, bj = 0, off = 0;
#pragma unroll 1
        for (int i = 0; i < 16; i++) {
            int cnt = 16 - i;
            if (idx < off + cnt) { bi = i; bj = i + idx - off; break; }
            off += cnt;
        }
        m0 = bi * 128; n0 = bj * 128;
    } else {
        m0 = blockIdx.y * 128; n0 = blockIdx.x * 128;
    }

    const size_t zAb = (size_t)blockIdx.z * sA * 2;   // bytes
    const size_t zBb = (size_t)blockIdx.z * sB * 2;
    const size_t zC  = (size_t)blockIdx.z * sC;

    // load geometry: 512 16B-chunks per 128x32 tile; this thread does 2 + 2
    const int r0 = tid >> 2;
    const int c0 = tid & 3;
    const uint32_t s_off0 = (uint32_t)r0 * ROWB + (uint32_t)c0 * 16;
    const size_t   a_off0 = (size_t)(m0 + r0) * 1024 + (size_t)c0 * 16;
    const size_t   b_off0 = (size_t)(n0 + r0) * 1024 + (size_t)c0 * 16;

    const uint32_t as_b[2] = { smem_u32(&As[0][0]), smem_u32(&As[1][0]) };
    const uint32_t bs_b[2] = { smem_u32(&Bs[0][0]), smem_u32(&Bs[1][0]) };

    const char* Ahb = (const char*)Ah + zAb;
    const char* Alb = (const char*)Al + zAb;
    const char* Bhb = (const char*)Bh + zBb;
    const char* Blb = (const char*)Bl + zBb;

    float acc[4][4][4];
#pragma unroll
    for (int i = 0; i < 4; i++)
#pragma unroll
        for (int j = 0; j < 4; j++)
#pragma unroll
            for (int k = 0; k < 4; k++) acc[i][j][k] = 0.f;

    const int rA = wm * 64 + (lane & 15);
    const int rB = wn * 32 + (lane & 15);
    const uint32_t half16 = (uint32_t)(lane >> 4) * 16;

    auto prefetch = [&](int it, int buf) {
        const int term = it >> 4;             // 0,1,2
        const int kc   = it & 15;
        const char* Ab  = (term == 2) ? Alb : Ahb;
        const char* Bbp = (term == 1) ? Blb : Bhb;
        const size_t koff = (size_t)kc * 64;
        uint32_t sa = as_b[buf] + s_off0;
        uint32_t sb = bs_b[buf] + s_off0;
        cpa16(sa,             Ab  + a_off0 + koff);
        cpa16(sa + 64 * ROWB, Ab  + a_off0 + (size_t)64 * 1024 + koff);
        cpa16(sb,             Bbp + b_off0 + koff);
        cpa16(sb + 64 * ROWB, Bbp + b_off0 + (size_t)64 * 1024 + koff);
    };

    prefetch(0, 0); CP_COMMIT();
    prefetch(1, 1); CP_COMMIT();

    for (int it = 0; it < NIT; ++it) {
        const int buf = it & 1;
        if (it == NIT - 1) { CP_WAIT(0); } else { CP_WAIT(1); }
        __syncthreads();

#pragma unroll
        for (int ks = 0; ks < 2; ks++) {
            uint32_t a[4][4];
            uint32_t b[2][4];
#pragma unroll
            for (int mi = 0; mi < 4; mi++) {
                uint32_t addr = as_b[buf] + (uint32_t)(rA + mi * 16) * ROWB
                              + (uint32_t)ks * 32 + half16;
                ldsm4(a[mi][0], a[mi][1], a[mi][2], a[mi][3], addr);
            }
#pragma unroll
            for (int nb = 0; nb < 2; nb++) {
                uint32_t addr = bs_b[buf] + (uint32_t)(rB + nb * 16) * ROWB
                              + (uint32_t)ks * 32 + half16;
                ldsm4(b[nb][0], b[nb][1], b[nb][2], b[nb][3], addr);
            }
#pragma unroll
            for (int mi = 0; mi < 4; mi++)
#pragma unroll
                for (int g = 0; g < 4; g++)
                    mma_bf16(acc[mi][g], a[mi], b[g >> 1][g & 1], b[g >> 1][(g & 1) + 2]);
        }
        __syncthreads();
        if (it + 2 < NIT) { prefetch(it + 2, buf); CP_COMMIT(); }
    }

    // ---------------- epilogue ----------------
    const int er = m0 + wm * 64 + (lane >> 2);
    const int ec = n0 + wn * 32 + (lane & 3) * 2;
#pragma unroll
    for (int mi = 0; mi < 4; mi++) {
#pragma unroll
        for (int g = 0; g < 4; g++) {
            const int r = er + mi * 16;
            const int c = ec + g * 8;
            if (EPI == 0) {
                float2 v0 = make_float2(acc[mi][g][0] * alpha, acc[mi][g][1] * alpha);
                float2 v1 = make_float2(acc[mi][g][2] * alpha, acc[mi][g][3] * alpha);
                *(float2*)(Cf + zC + (size_t)r * Ncols + c)       = v0;
                *(float2*)(Cf + zC + (size_t)(r + 8) * Ncols + c) = v1;
            } else {
#pragma unroll
                for (int hrow = 0; hrow < 2; hrow++) {
                    float v0 = fmaxf(acc[mi][g][2 * hrow + 0], 0.f);
                    float v1 = fmaxf(acc[mi][g][2 * hrow + 1], 0.f);
                    __nv_bfloat16 h0 = __float2bfloat16(v0), h1 = __float2bfloat16(v1);
                    __nv_bfloat16 l0 = __float2bfloat16(v0 - __bfloat162float(h0));
                    __nv_bfloat16 l1 = __float2bfloat16(v1 - __bfloat162float(h1));
                    __nv_bfloat162 hp = __halves2bfloat162(h0, h1);
                    __nv_bfloat162 lp = __halves2bfloat162(l0, l1);
                    const size_t o = (size_t)(r + 8 * hrow) * Ncols + c;
                    *(uint32_t*)(Ch + o) = *(uint32_t*)&hp;
                    *(uint32_t*)(Cl + o) = *(uint32_t*)&lp;
                }
            }
        }
    }
}

// ---------------- mirror: fill strictly-lower 128-blocks from upper --------
__global__ __launch_bounds__(256)
void mirror_kernel(float* __restrict__ S)
{
    __shared__ float t[32][33];
    const int pair = blockIdx.x >> 4;
    const int sub  = blockIdx.x & 15;
    const int b    = blockIdx.y;

    int bi = 0, bj = 0, off = 0;
#pragma unroll 1
    for (int i = 0; i < 16; i++) {
        int cnt = 15 - i;
        if (pair < off + cnt) { bi = i; bj = i + 1 + pair - off; break; }
        off += cnt;
    }
    const int m0 = bi * 128 + (sub >> 2) * 32;
    const int n0 = bj * 128 + (sub & 3) * 32;
    const size_t base = (size_t)b * Nn * Nn;

    const int tx = threadIdx.x & 31;
    const int ty = threadIdx.x >> 5;
#pragma unroll
    for (int j = 0; j < 32; j += 8)
        t[ty + j][tx] = S[base + (size_t)(m0 + ty + j) * Nn + n0 + tx];
    __syncthreads();
#pragma unroll
    for (int j = 0; j < 32; j += 8)
        S[base + (size_t)(n0 + ty + j) * Nn + m0 + tx] = t[tx][ty + j];
}

// ---------------- softmax stats / normalize --------------------------------
__global__ __launch_bounds__(256)
void row_stats_kernel(const float* __restrict__ S)
{
    const int row = blockIdx.x;
    const int tid = threadIdx.x;
    const float4* p = (const float4*)(S + (size_t)row * Nn);
    float4 v1 = p[tid];
    float4 v2 = p[tid + 256];

    float mx = fmaxf(fmaxf(fmaxf(v1.x, v1.y), fmaxf(v1.z, v1.w)),
                     fmaxf(fmaxf(v2.x, v2.y), fmaxf(v2.z, v2.w)));
    __shared__ float red[8];
#pragma unroll
    for (int o = 16; o > 0; o >>= 1)
        mx = fmaxf(mx, __shfl_xor_sync(0xffffffffu, mx, o));
    if ((tid & 31) == 0) red[tid >> 5] = mx;
    __syncthreads();
    mx = red[0];
#pragma unroll
    for (int i = 1; i < 8; i++) mx = fmaxf(mx, red[i]);
    __syncthreads();

    float s = __expf(v1.x - mx) + __expf(v1.y - mx) + __expf(v1.z - mx) + __expf(v1.w - mx)
            + __expf(v2.x - mx) + __expf(v2.y - mx) + __expf(v2.z - mx) + __expf(v2.w - mx);
#pragma unroll
    for (int o = 16; o > 0; o >>= 1)
        s += __shfl_xor_sync(0xffffffffu, s, o);
    if ((tid & 31) == 0) red[tid >> 5] = s;
    __syncthreads();
    if (tid == 0) {
        float t = 0.f;
#pragma unroll
        for (int i = 0; i < 8; i++) t += red[i];
        g_rmax[row] = mx;
        g_rinv[row] = 1.f / t;
    }
}

__global__ __launch_bounds__(256)
void norm_mask_kernel(float* __restrict__ S, const int* __restrict__ mask)
{
    const int row = blockIdx.x;
    const int tid = threadIdx.x;
    const int b   = row >> 11;
    const float mn = (float)mask[row];

    const float4* rmax = (const float4*)(g_rmax + ((size_t)b << 11));
    const float4* rinv = (const float4*)(g_rinv + ((size_t)b << 11));
    const int4*   mrow = (const int4*)(mask + ((size_t)b << 11));
    float4* p = (float4*)(S + (size_t)row * Nn);

#pragma unroll
    for (int jj = 0; jj < 2; jj++) {
        const int j = tid + jj * 256;
        float4 v  = p[j];
        float4 mx = rmax[j];
        float4 iv = rinv[j];
        int4   mm = mrow[j];
        v.x = __expf(v.x - mx.x) * iv.x * mn * (float)mm.x;
        v.y = __expf(v.y - mx.y) * iv.y * mn * (float)mm.y;
        v.z = __expf(v.z - mx.z) * iv.z * mn * (float)mm.z;
        v.w = __expf(v.w - mx.w) * iv.w * mn * (float)mm.w;
        p[j] = v;
    }
}

// ---------------- launch ---------------------------------------------------
extern "C" void kernel_launch(void* const* d_in, const int* in_sizes, int n_in,
                              void* d_out, int out_size)
{
    const float* ctx  = (const float*)d_in[0];   // [8, 2048, 512]
    const float* W    = (const float*)d_in[1];   // [16, 32, 512]
    const int*   mask = (const int*)d_in[2];     // [8, 2048]
    float* out = (float*)d_out;                  // [8, 2048, 2048]

    void *p_ch, *p_cl, *p_wh, *p_wl, *p_gh, *p_gl;
    cudaGetSymbolAddress(&p_ch, g_ctx_h); cudaGetSymbolAddress(&p_cl, g_ctx_l);
    cudaGetSymbolAddress(&p_wh, g_W_h);   cudaGetSymbolAddress(&p_wl, g_W_l);
    cudaGetSymbolAddress(&p_gh, g_G_h);   cudaGetSymbolAddress(&p_gl, g_G_l);
    __nv_bfloat16* Ch = (__nv_bfloat16*)p_ch; __nv_bfloat16* Cl = (__nv_bfloat16*)p_cl;
    __nv_bfloat16* Wh = (__nv_bfloat16*)p_wh; __nv_bfloat16* Wl = (__nv_bfloat16*)p_wl;
    __nv_bfloat16* Gh = (__nv_bfloat16*)p_gh; __nv_bfloat16* Gl = (__nv_bfloat16*)p_gl;

    // K0: split inputs into hi/lo bf16
    {
        int n4 = ROWS * Dd / 4;
        split_kernel<<<(n4 + 255) / 256, 256>>>(ctx, Ch, Cl, n4);
        int w4 = PH * Dd / 4;
        split_kernel<<<(w4 + 255) / 256, 256>>>(W, Wh, Wl, w4);
    }
    // K1: G = relu(ctx @ W^T) -> Gh/Gl bf16 split (fused epilogue)
    {
        dim3 grid(PH / 128, ROWS / 128, 1);
        mma_gemm<1,0><<<grid, 256>>>(Ch, Cl, Wh, Wl, nullptr, Gh, Gl,
                                     PH, 0, 0, 0, 1.0f);
    }
    // K2: S_b = G_b @ G_b^T / 16 -> d_out, upper-triangular blocks only
    {
        dim3 grid(136, 1, Bb);
        mma_gemm<0,1><<<grid, 256>>>(Gh, Gl, Gh, Gl, out, nullptr, nullptr,
                                     Nn, (size_t)Nn * PH, (size_t)Nn * PH,
                                     (size_t)Nn * Nn, 1.0f / (float)Pp);
    }
    // K2b: mirror upper -> lower
    {
        dim3 grid(120 * 16, Bb);
        mirror_kernel<<<grid, 256>>>(out);
    }
    // K3/K4: symmetric softmax (row stats == col stats) + mask
    row_stats_kernel<<<ROWS, 256>>>(out);
    norm_mask_kernel<<<ROWS, 256>>>(out, mask);
}

// round 8
// speedup vs baseline: 1.6778x; 1.0857x over previous
#include <cuda_runtime.h>
#include <cuda_bf16.h>
#include <stdint.h>
#include <math.h>

#define Bb 8
#define Nn 2048
#define Dd 512
#define Pp 16
#define PH 512
#define ROWS (Bb*Nn)   // 16384

// ---------------- scratch ---------------------------------------------------
__device__ __nv_bfloat16 g_ctx_h[(size_t)ROWS * Dd];
__device__ __nv_bfloat16 g_ctx_l[(size_t)ROWS * Dd];
__device__ __nv_bfloat16 g_W_h[(size_t)PH * Dd];
__device__ __nv_bfloat16 g_W_l[(size_t)PH * Dd];
__device__ __nv_bfloat16 g_G_h[(size_t)ROWS * PH];
__device__ __nv_bfloat16 g_G_l[(size_t)ROWS * PH];
__device__ float g_rmax[ROWS];
__device__ float g_rinv[ROWS];

// ---------------- small PTX helpers (base-ISA only) ------------------------
__device__ __forceinline__ uint32_t smem_u32(const void* p) {
    uint32_t a;
    asm("{ .reg .u64 t; cvta.to.shared.u64 t, %1; cvt.u32.u64 %0, t; }" : "=r"(a) : "l"(p));
    return a;
}
__device__ __forceinline__ void cpa16(uint32_t saddr, const void* g) {
    asm volatile("cp.async.cg.shared.global [%0], [%1], 16;" :: "r"(saddr), "l"(g));
}
#define CP_COMMIT() asm volatile("cp.async.commit_group;" ::: "memory")
#define CP_WAIT(n)  asm volatile("cp.async.wait_group %0;" :: "n"(n) : "memory")

__device__ __forceinline__ void ldsm4(uint32_t& d0, uint32_t& d1, uint32_t& d2, uint32_t& d3,
                                      uint32_t addr) {
    asm volatile("ldmatrix.sync.aligned.m8n8.x4.shared.b16 {%0,%1,%2,%3}, [%4];"
                 : "=r"(d0), "=r"(d1), "=r"(d2), "=r"(d3) : "r"(addr));
}
__device__ __forceinline__ void mma_bf16(float* c, const uint32_t* a, uint32_t b0, uint32_t b1) {
    asm volatile("mma.sync.aligned.m16n8k16.row.col.f32.bf16.bf16.f32 "
                 "{%0,%1,%2,%3}, {%4,%5,%6,%7}, {%8,%9}, {%0,%1,%2,%3};"
                 : "+f"(c[0]), "+f"(c[1]), "+f"(c[2]), "+f"(c[3])
                 : "r"(a[0]), "r"(a[1]), "r"(a[2]), "r"(a[3]), "r"(b0), "r"(b1));
}

// ---------------- split fp32 -> (hi, lo) bf16 ------------------------------
__global__ __launch_bounds__(256)
void split_kernel(const float* __restrict__ x, __nv_bfloat16* __restrict__ h,
                  __nv_bfloat16* __restrict__ l, int n4)
{
    int i = blockIdx.x * blockDim.x + threadIdx.x;
    if (i >= n4) return;
    float4 v = ((const float4*)x)[i];
    __nv_bfloat16 h0 = __float2bfloat16(v.x), h1 = __float2bfloat16(v.y);
    __nv_bfloat16 h2 = __float2bfloat16(v.z), h3 = __float2bfloat16(v.w);
    __nv_bfloat16 l0 = __float2bfloat16(v.x - __bfloat162float(h0));
    __nv_bfloat16 l1 = __float2bfloat16(v.y - __bfloat162float(h1));
    __nv_bfloat16 l2 = __float2bfloat16(v.z - __bfloat162float(h2));
    __nv_bfloat16 l3 = __float2bfloat16(v.w - __bfloat162float(h3));
    __nv_bfloat162 hp0 = __halves2bfloat162(h0, h1), hp1 = __halves2bfloat162(h2, h3);
    __nv_bfloat162 lp0 = __halves2bfloat162(l0, l1), lp1 = __halves2bfloat162(l2, l3);
    uint2 hv, lv;
    hv.x = *(uint32_t*)&hp0; hv.y = *(uint32_t*)&hp1;
    lv.x = *(uint32_t*)&lp0; lv.y = *(uint32_t*)&lp1;
    ((uint2*)h)[i] = hv;
    ((uint2*)l)[i] = lv;
}

// ---------------- mma.sync GEMM, 4-stage pipeline, 1 barrier/iter ----------
// C = f(alpha * A·B^T); 3 accumulation passes Ahi·Bhi^T + Ahi·Blo^T + Alo·Bhi^T.
// EPI=0: fp32 * alpha.  EPI=1: relu + split into (Ch, Cl).
// SYM=1: blockIdx.x in [0,136) -> upper-triangular (bi<=bj) 128-block.
#define LDS_ROW 40          // 32 bf16 + 8 pad = 80 bytes
#define ROWB    80
#define NIT     48          // 3 terms * (512/32)
#define STAGE_B 20480       // (A 10240 + B 10240) bytes per stage
#define GEMM_SMEM (4*STAGE_B)

template<int EPI, int SYM>
__global__ __launch_bounds__(256, 2)
void mma_gemm(const __nv_bfloat16* __restrict__ Ah, const __nv_bfloat16* __restrict__ Al,
              const __nv_bfloat16* __restrict__ Bh, const __nv_bfloat16* __restrict__ Bl,
              float* __restrict__ Cf, __nv_bfloat16* __restrict__ Ch, __nv_bfloat16* __restrict__ Cl,
              int Ncols, size_t sA, size_t sB, size_t sC, float alpha)
{
    extern __shared__ char dsm[];

    const int tid  = threadIdx.x;
    const int wid  = tid >> 5;
    const int lane = tid & 31;
    const int wm   = wid >> 2;        // 0..1  (M warp row, 64 rows)
    const int wn   = wid & 3;         // 0..3  (N warp col, 32 cols)

    int m0, n0;
    if (SYM) {
        int idx = blockIdx.x, bi = 0, bj = 0, off = 0;
#pragma unroll 1
        for (int i = 0; i < 16; i++) {
            int cnt = 16 - i;
            if (idx < off + cnt) { bi = i; bj = i + idx - off; break; }
            off += cnt;
        }
        m0 = bi * 128; n0 = bj * 128;
    } else {
        m0 = blockIdx.y * 128; n0 = blockIdx.x * 128;
    }

    const size_t zAb = (size_t)blockIdx.z * sA * 2;   // bytes
    const size_t zBb = (size_t)blockIdx.z * sB * 2;
    const size_t zC  = (size_t)blockIdx.z * sC;

    // load geometry: 512 16B-chunks per 128x32 tile; this thread does 2 + 2
    const int r0 = tid >> 2;
    const int c0 = tid & 3;
    const uint32_t s_off0 = (uint32_t)r0 * ROWB + (uint32_t)c0 * 16;
    const size_t   a_off0 = (size_t)(m0 + r0) * 1024 + (size_t)c0 * 16;
    const size_t   b_off0 = (size_t)(n0 + r0) * 1024 + (size_t)c0 * 16;

    uint32_t as_b[4], bs_b[4];
#pragma unroll
    for (int s = 0; s < 4; s++) {
        as_b[s] = smem_u32(dsm + s * STAGE_B);
        bs_b[s] = smem_u32(dsm + s * STAGE_B + 10240);
    }

    const char* Ahb = (const char*)Ah + zAb;
    const char* Alb = (const char*)Al + zAb;
    const char* Bhb = (const char*)Bh + zBb;
    const char* Blb = (const char*)Bl + zBb;

    float acc[4][4][4];
#pragma unroll
    for (int i = 0; i < 4; i++)
#pragma unroll
        for (int j = 0; j < 4; j++)
#pragma unroll
            for (int k = 0; k < 4; k++) acc[i][j][k] = 0.f;

    const int rA = wm * 64 + (lane & 15);
    const int rB = wn * 32 + (lane & 15);
    const uint32_t half16 = (uint32_t)(lane >> 4) * 16;

    auto prefetch = [&](int it, int buf) {
        const int term = it >> 4;             // 0,1,2
        const int kc   = it & 15;
        const char* Ab  = (term == 2) ? Alb : Ahb;
        const char* Bbp = (term == 1) ? Blb : Bhb;
        const size_t koff = (size_t)kc * 64;
        uint32_t sa = as_b[buf] + s_off0;
        uint32_t sb = bs_b[buf] + s_off0;
        cpa16(sa,             Ab  + a_off0 + koff);
        cpa16(sa + 64 * ROWB, Ab  + a_off0 + (size_t)64 * 1024 + koff);
        cpa16(sb,             Bbp + b_off0 + koff);
        cpa16(sb + 64 * ROWB, Bbp + b_off0 + (size_t)64 * 1024 + koff);
    };

    prefetch(0, 0); CP_COMMIT();
    prefetch(1, 1); CP_COMMIT();
    prefetch(2, 2); CP_COMMIT();

#pragma unroll 4
    for (int it = 0; it < NIT; ++it) {
        const int buf = it & 3;               // compile-time under unroll-4
        if (it < NIT - 2) { CP_WAIT(2); } else { CP_WAIT(0); }
        __syncthreads();                      // single barrier per iteration

#pragma unroll
        for (int ks = 0; ks < 2; ks++) {
            uint32_t a[4][4];
            uint32_t b[2][4];
#pragma unroll
            for (int mi = 0; mi < 4; mi++) {
                uint32_t addr = as_b[buf] + (uint32_t)(rA + mi * 16) * ROWB
                              + (uint32_t)ks * 32 + half16;
                ldsm4(a[mi][0], a[mi][1], a[mi][2], a[mi][3], addr);
            }
#pragma unroll
            for (int nb = 0; nb < 2; nb++) {
                uint32_t addr = bs_b[buf] + (uint32_t)(rB + nb * 16) * ROWB
                              + (uint32_t)ks * 32 + half16;
                ldsm4(b[nb][0], b[nb][1], b[nb][2], b[nb][3], addr);
            }
#pragma unroll
            for (int mi = 0; mi < 4; mi++)
#pragma unroll
                for (int g = 0; g < 4; g++)
                    mma_bf16(acc[mi][g], a[mi], b[g >> 1][g & 1], b[g >> 1][(g & 1) + 2]);
        }
        // prefetch target (it+3)%4 == (it-1)%4: consumed at it-1; every warp
        // passed compute(it-1) before crossing this iteration's barrier.
        if (it + 3 < NIT) { prefetch(it + 3, (it + 3) & 3); CP_COMMIT(); }
    }

    // ---------------- epilogue ----------------
    const int er = m0 + wm * 64 + (lane >> 2);
    const int ec = n0 + wn * 32 + (lane & 3) * 2;
#pragma unroll
    for (int mi = 0; mi < 4; mi++) {
#pragma unroll
        for (int g = 0; g < 4; g++) {
            const int r = er + mi * 16;
            const int c = ec + g * 8;
            if (EPI == 0) {
                float2 v0 = make_float2(acc[mi][g][0] * alpha, acc[mi][g][1] * alpha);
                float2 v1 = make_float2(acc[mi][g][2] * alpha, acc[mi][g][3] * alpha);
                *(float2*)(Cf + zC + (size_t)r * Ncols + c)       = v0;
                *(float2*)(Cf + zC + (size_t)(r + 8) * Ncols + c) = v1;
            } else {
#pragma unroll
                for (int hrow = 0; hrow < 2; hrow++) {
                    float v0 = fmaxf(acc[mi][g][2 * hrow + 0], 0.f);
                    float v1 = fmaxf(acc[mi][g][2 * hrow + 1], 0.f);
                    __nv_bfloat16 h0 = __float2bfloat16(v0), h1 = __float2bfloat16(v1);
                    __nv_bfloat16 l0 = __float2bfloat16(v0 - __bfloat162float(h0));
                    __nv_bfloat16 l1 = __float2bfloat16(v1 - __bfloat162float(h1));
                    __nv_bfloat162 hp = __halves2bfloat162(h0, h1);
                    __nv_bfloat162 lp = __halves2bfloat162(l0, l1);
                    const size_t o = (size_t)(r + 8 * hrow) * Ncols + c;
                    *(uint32_t*)(Ch + o) = *(uint32_t*)&hp;
                    *(uint32_t*)(Cl + o) = *(uint32_t*)&lp;
                }
            }
        }
    }
}

// ---------------- mirror: fill strictly-lower 128-blocks from upper --------
__global__ __launch_bounds__(256)
void mirror_kernel(float* __restrict__ S)
{
    __shared__ float t[32][33];
    const int pair = blockIdx.x >> 4;
    const int sub  = blockIdx.x & 15;
    const int b    = blockIdx.y;

    int bi = 0, bj = 0, off = 0;
#pragma unroll 1
    for (int i = 0; i < 16; i++) {
        int cnt = 15 - i;
        if (pair < off + cnt) { bi = i; bj = i + 1 + pair - off; break; }
        off += cnt;
    }
    const int m0 = bi * 128 + (sub >> 2) * 32;
    const int n0 = bj * 128 + (sub & 3) * 32;
    const size_t base = (size_t)b * Nn * Nn;

    const int tx = threadIdx.x & 31;
    const int ty = threadIdx.x >> 5;
#pragma unroll
    for (int j = 0; j < 32; j += 8)
        t[ty + j][tx] = S[base + (size_t)(m0 + ty + j) * Nn + n0 + tx];
    __syncthreads();
#pragma unroll
    for (int j = 0; j < 32; j += 8)
        S[base + (size_t)(n0 + ty + j) * Nn + m0 + tx] = t[tx][ty + j];
}

// ---------------- softmax stats / normalize --------------------------------
__global__ __launch_bounds__(256)
void row_stats_kernel(const float* __restrict__ S)
{
    const int row = blockIdx.x;
    const int tid = threadIdx.x;
    const float4* p = (const float4*)(S + (size_t)row * Nn);
    float4 v1 = p[tid];
    float4 v2 = p[tid + 256];

    float mx = fmaxf(fmaxf(fmaxf(v1.x, v1.y), fmaxf(v1.z, v1.w)),
                     fmaxf(fmaxf(v2.x, v2.y), fmaxf(v2.z, v2.w)));
    __shared__ float red[8];
#pragma unroll
    for (int o = 16; o > 0; o >>= 1)
        mx = fmaxf(mx, __shfl_xor_sync(0xffffffffu, mx, o));
    if ((tid & 31) == 0) red[tid >> 5] = mx;
    __syncthreads();
    mx = red[0];
#pragma unroll
    for (int i = 1; i < 8; i++) mx = fmaxf(mx, red[i]);
    __syncthreads();

    float s = __expf(v1.x - mx) + __expf(v1.y - mx) + __expf(v1.z - mx) + __expf(v1.w - mx)
            + __expf(v2.x - mx) + __expf(v2.y - mx) + __expf(v2.z - mx) + __expf(v2.w - mx);
#pragma unroll
    for (int o = 16; o > 0; o >>= 1)
        s += __shfl_xor_sync(0xffffffffu, s, o);
    if ((tid & 31) == 0) red[tid >> 5] = s;
    __syncthreads();
    if (tid == 0) {
        float t = 0.f;
#pragma unroll
        for (int i = 0; i < 8; i++) t += red[i];
        g_rmax[row] = mx;
        g_rinv[row] = 1.f / t;
    }
}

__global__ __launch_bounds__(256)
void norm_mask_kernel(float* __restrict__ S, const int* __restrict__ mask)
{
    const int row = blockIdx.x;
    const int tid = threadIdx.x;
    const int b   = row >> 11;
    const float mn = (float)mask[row];

    const float4* rmax = (const float4*)(g_rmax + ((size_t)b << 11));
    const float4* rinv = (const float4*)(g_rinv + ((size_t)b << 11));
    const int4*   mrow = (const int4*)(mask + ((size_t)b << 11));
    float4* p = (float4*)(S + (size_t)row * Nn);

#pragma unroll
    for (int jj = 0; jj < 2; jj++) {
        const int j = tid + jj * 256;
        float4 v  = p[j];
        float4 mx = rmax[j];
        float4 iv = rinv[j];
        int4   mm = mrow[j];
        v.x = __expf(v.x - mx.x) * iv.x * mn * (float)mm.x;
        v.y = __expf(v.y - mx.y) * iv.y * mn * (float)mm.y;
        v.z = __expf(v.z - mx.z) * iv.z * mn * (float)mm.z;
        v.w = __expf(v.w - mx.w) * iv.w * mn * (float)mm.w;
        p[j] = v;
    }
}

// ---------------- launch ---------------------------------------------------
extern "C" void kernel_launch(void* const* d_in, const int* in_sizes, int n_in,
                              void* d_out, int out_size)
{
    const float* ctx  = (const float*)d_in[0];   // [8, 2048, 512]
    const float* W    = (const float*)d_in[1];   // [16, 32, 512]
    const int*   mask = (const int*)d_in[2];     // [8, 2048]
    float* out = (float*)d_out;                  // [8, 2048, 2048]

    void *p_ch, *p_cl, *p_wh, *p_wl, *p_gh, *p_gl;
    cudaGetSymbolAddress(&p_ch, g_ctx_h); cudaGetSymbolAddress(&p_cl, g_ctx_l);
    cudaGetSymbolAddress(&p_wh, g_W_h);   cudaGetSymbolAddress(&p_wl, g_W_l);
    cudaGetSymbolAddress(&p_gh, g_G_h);   cudaGetSymbolAddress(&p_gl, g_G_l);
    __nv_bfloat16* Ch = (__nv_bfloat16*)p_ch; __nv_bfloat16* Cl = (__nv_bfloat16*)p_cl;
    __nv_bfloat16* Wh = (__nv_bfloat16*)p_wh; __nv_bfloat16* Wl = (__nv_bfloat16*)p_wl;
    __nv_bfloat16* Gh = (__nv_bfloat16*)p_gh; __nv_bfloat16* Gl = (__nv_bfloat16*)p_gl;

    cudaFuncSetAttribute(mma_gemm<0,1>, cudaFuncAttributeMaxDynamicSharedMemorySize, GEMM_SMEM);
    cudaFuncSetAttribute(mma_gemm<1,0>, cudaFuncAttributeMaxDynamicSharedMemorySize, GEMM_SMEM);

    // K0: split inputs into hi/lo bf16
    {
        int n4 = ROWS * Dd / 4;
        split_kernel<<<(n4 + 255) / 256, 256>>>(ctx, Ch, Cl, n4);
        int w4 = PH * Dd / 4;
        split_kernel<<<(w4 + 255) / 256, 256>>>(W, Wh, Wl, w4);
    }
    // K1: G = relu(ctx @ W^T) -> Gh/Gl bf16 split (fused epilogue)
    {
        dim3 grid(PH / 128, ROWS / 128, 1);
        mma_gemm<1,0><<<grid, 256, GEMM_SMEM>>>(Ch, Cl, Wh, Wl, nullptr, Gh, Gl,
                                                PH, 0, 0, 0, 1.0f);
    }
    // K2: S_b = G_b @ G_b^T / 16 -> d_out, upper-triangular blocks only
    {
        dim3 grid(136, 1, Bb);
        mma_gemm<0,1><<<grid, 256, GEMM_SMEM>>>(Gh, Gl, Gh, Gl, out, nullptr, nullptr,
                                                Nn, (size_t)Nn * PH, (size_t)Nn * PH,
                                                (size_t)Nn * Nn, 1.0f / (float)Pp);
    }
    // K2b: mirror upper -> lower
    {
        dim3 grid(120 * 16, Bb);
        mirror_kernel<<<grid, 256>>>(out);
    }
    // K3/K4: symmetric softmax (row stats == col stats) + mask
    row_stats_kernel<<<ROWS, 256>>>(out);
    norm_mask_kernel<<<ROWS, 256>>>(out, mask);
}

// round 9
// speedup vs baseline: 1.7493x; 1.0426x over previous
#include <cuda_runtime.h>
#include <cuda_bf16.h>
#include <stdint.h>
#include <math.h>

#define Bb 8
#define Nn 2048
#define Dd 512
#define Pp 16
#define PH 512
#define ROWS (Bb*Nn)   // 16384

// ---------------- scratch ---------------------------------------------------
__device__ __nv_bfloat16 g_ctx_h[(size_t)ROWS * Dd];
__device__ __nv_bfloat16 g_ctx_l[(size_t)ROWS * Dd];
__device__ __nv_bfloat16 g_W_h[(size_t)PH * Dd];
__device__ __nv_bfloat16 g_W_l[(size_t)PH * Dd];
__device__ __nv_bfloat16 g_G_h[(size_t)ROWS * PH];
__device__ __nv_bfloat16 g_G_l[(size_t)ROWS * PH];
__device__ float g_rmax[ROWS];
__device__ float g_rinv[ROWS];

// ---------------- small PTX helpers (base-ISA only) ------------------------
__device__ __forceinline__ uint32_t smem_u32(const void* p) {
    uint32_t a;
    asm("{ .reg .u64 t; cvta.to.shared.u64 t, %1; cvt.u32.u64 %0, t; }" : "=r"(a) : "l"(p));
    return a;
}
__device__ __forceinline__ void cpa16(uint32_t saddr, const void* g) {
    asm volatile("cp.async.cg.shared.global [%0], [%1], 16;" :: "r"(saddr), "l"(g));
}
#define CP_COMMIT() asm volatile("cp.async.commit_group;" ::: "memory")
#define CP_WAIT(n)  asm volatile("cp.async.wait_group %0;" :: "n"(n) : "memory")

__device__ __forceinline__ void ldsm4(uint32_t& d0, uint32_t& d1, uint32_t& d2, uint32_t& d3,
                                      uint32_t addr) {
    asm volatile("ldmatrix.sync.aligned.m8n8.x4.shared.b16 {%0,%1,%2,%3}, [%4];"
                 : "=r"(d0), "=r"(d1), "=r"(d2), "=r"(d3) : "r"(addr));
}
__device__ __forceinline__ void mma_bf16(float* c, const uint32_t* a, uint32_t b0, uint32_t b1) {
    asm volatile("mma.sync.aligned.m16n8k16.row.col.f32.bf16.bf16.f32 "
                 "{%0,%1,%2,%3}, {%4,%5,%6,%7}, {%8,%9}, {%0,%1,%2,%3};"
                 : "+f"(c[0]), "+f"(c[1]), "+f"(c[2]), "+f"(c[3])
                 : "r"(a[0]), "r"(a[1]), "r"(a[2]), "r"(a[3]), "r"(b0), "r"(b1));
}

// ---------------- split fp32 -> (hi, lo) bf16 ------------------------------
__global__ __launch_bounds__(256)
void split_kernel(const float* __restrict__ x, __nv_bfloat16* __restrict__ h,
                  __nv_bfloat16* __restrict__ l, int n4)
{
    int i = blockIdx.x * blockDim.x + threadIdx.x;
    if (i >= n4) return;
    float4 v = ((const float4*)x)[i];
    __nv_bfloat16 h0 = __float2bfloat16(v.x), h1 = __float2bfloat16(v.y);
    __nv_bfloat16 h2 = __float2bfloat16(v.z), h3 = __float2bfloat16(v.w);
    __nv_bfloat16 l0 = __float2bfloat16(v.x - __bfloat162float(h0));
    __nv_bfloat16 l1 = __float2bfloat16(v.y - __bfloat162float(h1));
    __nv_bfloat16 l2 = __float2bfloat16(v.z - __bfloat162float(h2));
    __nv_bfloat16 l3 = __float2bfloat16(v.w - __bfloat162float(h3));
    __nv_bfloat162 hp0 = __halves2bfloat162(h0, h1), hp1 = __halves2bfloat162(h2, h3);
    __nv_bfloat162 lp0 = __halves2bfloat162(l0, l1), lp1 = __halves2bfloat162(l2, l3);
    uint2 hv, lv;
    hv.x = *(uint32_t*)&hp0; hv.y = *(uint32_t*)&hp1;
    lv.x = *(uint32_t*)&lp0; lv.y = *(uint32_t*)&lp1;
    ((uint2*)h)[i] = hv;
    ((uint2*)l)[i] = lv;
}

// ---------------- mma.sync GEMM, BK=64, 3-stage, 1 barrier/iter ------------
// C = f(alpha * A·B^T); 3 accumulation passes Ahi·Bhi^T + Ahi·Blo^T + Alo·Bhi^T.
// EPI=0: fp32 * alpha.  EPI=1: relu + split into (Ch, Cl).
// SYM=1: blockIdx.x in [0,136) -> upper-triangular (bi<=bj) 128-block.
#define ROWB    144         // 64 bf16 (128B) + 16B pad
#define NIT     24          // 3 terms * (512/64)
#define MAT_B   18432       // 128*ROWB bytes per matrix tile
#define STAGE_B (2*MAT_B)   // A + B
#define GEMM_SMEM (3*STAGE_B)

template<int EPI, int SYM>
__global__ __launch_bounds__(256, 2)
void mma_gemm(const __nv_bfloat16* __restrict__ Ah, const __nv_bfloat16* __restrict__ Al,
              const __nv_bfloat16* __restrict__ Bh, const __nv_bfloat16* __restrict__ Bl,
              float* __restrict__ Cf, __nv_bfloat16* __restrict__ Ch, __nv_bfloat16* __restrict__ Cl,
              int Ncols, size_t sA, size_t sB, size_t sC, float alpha)
{
    extern __shared__ char dsm[];

    const int tid  = threadIdx.x;
    const int wid  = tid >> 5;
    const int lane = tid & 31;
    const int wm   = wid >> 2;        // 0..1  (M warp row, 64 rows)
    const int wn   = wid & 3;         // 0..3  (N warp col, 32 cols)

    int m0, n0;
    if (SYM) {
        int idx = blockIdx.x, bi = 0, bj = 0, off = 0;
#pragma unroll 1
        for (int i = 0; i < 16; i++) {
            int cnt = 16 - i;
            if (idx < off + cnt) { bi = i; bj = i + idx - off; break; }
            off += cnt;
        }
        m0 = bi * 128; n0 = bj * 128;
    } else {
        m0 = blockIdx.y * 128; n0 = blockIdx.x * 128;
    }

    const size_t zAb = (size_t)blockIdx.z * sA * 2;   // bytes
    const size_t zBb = (size_t)blockIdx.z * sB * 2;
    const size_t zC  = (size_t)blockIdx.z * sC;

    // load geometry: 128x64 tile = 1024 16B-chunks per matrix; 4 + 4 per thread
    const int r0 = tid >> 3;          // row 0..31
    const int c0 = tid & 7;           // 16B chunk within 128B row
    const uint32_t s_off0 = (uint32_t)r0 * ROWB + (uint32_t)c0 * 16;
    const size_t   a_off0 = (size_t)(m0 + r0) * 1024 + (size_t)c0 * 16;  // K row = 1024B
    const size_t   b_off0 = (size_t)(n0 + r0) * 1024 + (size_t)c0 * 16;

    uint32_t as_b[3], bs_b[3];
#pragma unroll
    for (int s = 0; s < 3; s++) {
        as_b[s] = smem_u32(dsm + s * STAGE_B);
        bs_b[s] = smem_u32(dsm + s * STAGE_B + MAT_B);
    }

    const char* Ahb = (const char*)Ah + zAb;
    const char* Alb = (const char*)Al + zAb;
    const char* Bhb = (const char*)Bh + zBb;
    const char* Blb = (const char*)Bl + zBb;

    float acc[4][4][4];
#pragma unroll
    for (int i = 0; i < 4; i++)
#pragma unroll
        for (int j = 0; j < 4; j++)
#pragma unroll
            for (int k = 0; k < 4; k++) acc[i][j][k] = 0.f;

    const int rA = wm * 64 + (lane & 15);
    const int rB = wn * 32 + (lane & 15);
    const uint32_t half16 = (uint32_t)(lane >> 4) * 16;

    auto prefetch = [&](int it, int buf) {
        const int term = it >> 3;             // 0,1,2
        const int kc   = it & 7;
        const char* Ab  = (term == 2) ? Alb : Ahb;
        const char* Bbp = (term == 1) ? Blb : Bhb;
        const size_t koff = (size_t)kc * 128; // 64 bf16 = 128B
        uint32_t sa = as_b[buf] + s_off0;
        uint32_t sb = bs_b[buf] + s_off0;
#pragma unroll
        for (int q = 0; q < 4; q++) {
            cpa16(sa + q * 32 * ROWB, Ab  + a_off0 + (size_t)(q * 32) * 1024 + koff);
            cpa16(sb + q * 32 * ROWB, Bbp + b_off0 + (size_t)(q * 32) * 1024 + koff);
        }
    };

    prefetch(0, 0); CP_COMMIT();
    prefetch(1, 1); CP_COMMIT();

#pragma unroll 3
    for (int it = 0; it < NIT; ++it) {
        const int buf = it % 3;               // compile-time under unroll-3
        if (it < NIT - 1) { CP_WAIT(1); } else { CP_WAIT(0); }
        __syncthreads();                      // single barrier per iteration

#pragma unroll
        for (int ks = 0; ks < 4; ks++) {
            uint32_t a[4][4];
            uint32_t b[2][4];
#pragma unroll
            for (int mi = 0; mi < 4; mi++) {
                uint32_t addr = as_b[buf] + (uint32_t)(rA + mi * 16) * ROWB
                              + (uint32_t)ks * 32 + half16;
                ldsm4(a[mi][0], a[mi][1], a[mi][2], a[mi][3], addr);
            }
#pragma unroll
            for (int nb = 0; nb < 2; nb++) {
                uint32_t addr = bs_b[buf] + (uint32_t)(rB + nb * 16) * ROWB
                              + (uint32_t)ks * 32 + half16;
                ldsm4(b[nb][0], b[nb][1], b[nb][2], b[nb][3], addr);
            }
#pragma unroll
            for (int mi = 0; mi < 4; mi++)
#pragma unroll
                for (int g = 0; g < 4; g++)
                    mma_bf16(acc[mi][g], a[mi], b[g >> 1][g & 1], b[g >> 1][(g & 1) + 2]);
        }
        // prefetch target (it+2)%3 == (it-1)%3: consumed at it-1; every warp
        // passed compute(it-1) before crossing this iteration's barrier.
        if (it + 2 < NIT) { prefetch(it + 2, (it + 2) % 3); CP_COMMIT(); }
    }

    // ---------------- epilogue ----------------
    const int er = m0 + wm * 64 + (lane >> 2);
    const int ec = n0 + wn * 32 + (lane & 3) * 2;
#pragma unroll
    for (int mi = 0; mi < 4; mi++) {
#pragma unroll
        for (int g = 0; g < 4; g++) {
            const int r = er + mi * 16;
            const int c = ec + g * 8;
            if (EPI == 0) {
                float2 v0 = make_float2(acc[mi][g][0] * alpha, acc[mi][g][1] * alpha);
                float2 v1 = make_float2(acc[mi][g][2] * alpha, acc[mi][g][3] * alpha);
                *(float2*)(Cf + zC + (size_t)r * Ncols + c)       = v0;
                *(float2*)(Cf + zC + (size_t)(r + 8) * Ncols + c) = v1;
            } else {
#pragma unroll
                for (int hrow = 0; hrow < 2; hrow++) {
                    float v0 = fmaxf(acc[mi][g][2 * hrow + 0], 0.f);
                    float v1 = fmaxf(acc[mi][g][2 * hrow + 1], 0.f);
                    __nv_bfloat16 h0 = __float2bfloat16(v0), h1 = __float2bfloat16(v1);
                    __nv_bfloat16 l0 = __float2bfloat16(v0 - __bfloat162float(h0));
                    __nv_bfloat16 l1 = __float2bfloat16(v1 - __bfloat162float(h1));
                    __nv_bfloat162 hp = __halves2bfloat162(h0, h1);
                    __nv_bfloat162 lp = __halves2bfloat162(l0, l1);
                    const size_t o = (size_t)(r + 8 * hrow) * Ncols + c;
                    *(uint32_t*)(Ch + o) = *(uint32_t*)&hp;
                    *(uint32_t*)(Cl + o) = *(uint32_t*)&lp;
                }
            }
        }
    }
}

// ---------------- mirror: fill strictly-lower 128-blocks from upper --------
__global__ __launch_bounds__(256)
void mirror_kernel(float* __restrict__ S)
{
    __shared__ float t[32][33];
    const int pair = blockIdx.x >> 4;
    const int sub  = blockIdx.x & 15;
    const int b    = blockIdx.y;

    int bi = 0, bj = 0, off = 0;
#pragma unroll 1
    for (int i = 0; i < 16; i++) {
        int cnt = 15 - i;
        if (pair < off + cnt) { bi = i; bj = i + 1 + pair - off; break; }
        off += cnt;
    }
    const int m0 = bi * 128 + (sub >> 2) * 32;
    const int n0 = bj * 128 + (sub & 3) * 32;
    const size_t base = (size_t)b * Nn * Nn;

    const int tx = threadIdx.x & 31;
    const int ty = threadIdx.x >> 5;
#pragma unroll
    for (int j = 0; j < 32; j += 8)
        t[ty + j][tx] = S[base + (size_t)(m0 + ty + j) * Nn + n0 + tx];
    __syncthreads();
#pragma unroll
    for (int j = 0; j < 32; j += 8)
        S[base + (size_t)(n0 + ty + j) * Nn + m0 + tx] = t[tx][ty + j];
}

// ---------------- softmax stats / normalize --------------------------------
__global__ __launch_bounds__(256)
void row_stats_kernel(const float* __restrict__ S)
{
    const int row = blockIdx.x;
    const int tid = threadIdx.x;
    const float4* p = (const float4*)(S + (size_t)row * Nn);
    float4 v1 = p[tid];
    float4 v2 = p[tid + 256];

    float mx = fmaxf(fmaxf(fmaxf(v1.x, v1.y), fmaxf(v1.z, v1.w)),
                     fmaxf(fmaxf(v2.x, v2.y), fmaxf(v2.z, v2.w)));
    __shared__ float red[8];
#pragma unroll
    for (int o = 16; o > 0; o >>= 1)
        mx = fmaxf(mx, __shfl_xor_sync(0xffffffffu, mx, o));
    if ((tid & 31) == 0) red[tid >> 5] = mx;
    __syncthreads();
    mx = red[0];
#pragma unroll
    for (int i = 1; i < 8; i++) mx = fmaxf(mx, red[i]);
    __syncthreads();

    float s = __expf(v1.x - mx) + __expf(v1.y - mx) + __expf(v1.z - mx) + __expf(v1.w - mx)
            + __expf(v2.x - mx) + __expf(v2.y - mx) + __expf(v2.z - mx) + __expf(v2.w - mx);
#pragma unroll
    for (int o = 16; o > 0; o >>= 1)
        s += __shfl_xor_sync(0xffffffffu, s, o);
    if ((tid & 31) == 0) red[tid >> 5] = s;
    __syncthreads();
    if (tid == 0) {
        float t = 0.f;
#pragma unroll
        for (int i = 0; i < 8; i++) t += red[i];
        g_rmax[row] = mx;
        g_rinv[row] = 1.f / t;
    }
}

__global__ __launch_bounds__(256)
void norm_mask_kernel(float* __restrict__ S, const int* __restrict__ mask)
{
    const int row = blockIdx.x;
    const int tid = threadIdx.x;
    const int b   = row >> 11;
    const float mn = (float)mask[row];

    const float4* rmax = (const float4*)(g_rmax + ((size_t)b << 11));
    const float4* rinv = (const float4*)(g_rinv + ((size_t)b << 11));
    const int4*   mrow = (const int4*)(mask + ((size_t)b << 11));
    float4* p = (float4*)(S + (size_t)row * Nn);

#pragma unroll
    for (int jj = 0; jj < 2; jj++) {
        const int j = tid + jj * 256;
        float4 v  = p[j];
        float4 mx = rmax[j];
        float4 iv = rinv[j];
        int4   mm = mrow[j];
        v.x = __expf(v.x - mx.x) * iv.x * mn * (float)mm.x;
        v.y = __expf(v.y - mx.y) * iv.y * mn * (float)mm.y;
        v.z = __expf(v.z - mx.z) * iv.z * mn * (float)mm.z;
        v.w = __expf(v.w - mx.w) * iv.w * mn * (float)mm.w;
        p[j] = v;
    }
}

// ---------------- launch ---------------------------------------------------
extern "C" void kernel_launch(void* const* d_in, const int* in_sizes, int n_in,
                              void* d_out, int out_size)
{
    const float* ctx  = (const float*)d_in[0];   // [8, 2048, 512]
    const float* W    = (const float*)d_in[1];   // [16, 32, 512]
    const int*   mask = (const int*)d_in[2];     // [8, 2048]
    float* out = (float*)d_out;                  // [8, 2048, 2048]

    void *p_ch, *p_cl, *p_wh, *p_wl, *p_gh, *p_gl;
    cudaGetSymbolAddress(&p_ch, g_ctx_h); cudaGetSymbolAddress(&p_cl, g_ctx_l);
    cudaGetSymbolAddress(&p_wh, g_W_h);   cudaGetSymbolAddress(&p_wl, g_W_l);
    cudaGetSymbolAddress(&p_gh, g_G_h);   cudaGetSymbolAddress(&p_gl, g_G_l);
    __nv_bfloat16* Ch = (__nv_bfloat16*)p_ch; __nv_bfloat16* Cl = (__nv_bfloat16*)p_cl;
    __nv_bfloat16* Wh = (__nv_bfloat16*)p_wh; __nv_bfloat16* Wl = (__nv_bfloat16*)p_wl;
    __nv_bfloat16* Gh = (__nv_bfloat16*)p_gh; __nv_bfloat16* Gl = (__nv_bfloat16*)p_gl;

    cudaFuncSetAttribute(mma_gemm<0,1>, cudaFuncAttributeMaxDynamicSharedMemorySize, GEMM_SMEM);
    cudaFuncSetAttribute(mma_gemm<1,0>, cudaFuncAttributeMaxDynamicSharedMemorySize, GEMM_SMEM);

    // K0: split inputs into hi/lo bf16
    {
        int n4 = ROWS * Dd / 4;
        split_kernel<<<(n4 + 255) / 256, 256>>>(ctx, Ch, Cl, n4);
        int w4 = PH * Dd / 4;
        split_kernel<<<(w4 + 255) / 256, 256>>>(W, Wh, Wl, w4);
    }
    // K1: G = relu(ctx @ W^T) -> Gh/Gl bf16 split (fused epilogue)
    {
        dim3 grid(PH / 128, ROWS / 128, 1);
        mma_gemm<1,0><<<grid, 256, GEMM_SMEM>>>(Ch, Cl, Wh, Wl, nullptr, Gh, Gl,
                                                PH, 0, 0, 0, 1.0f);
    }
    // K2: S_b = G_b @ G_b^T / 16 -> d_out, upper-triangular blocks only
    {
        dim3 grid(136, 1, Bb);
        mma_gemm<0,1><<<grid, 256, GEMM_SMEM>>>(Gh, Gl, Gh, Gl, out, nullptr, nullptr,
                                                Nn, (size_t)Nn * PH, (size_t)Nn * PH,
                                                (size_t)Nn * Nn, 1.0f / (float)Pp);
    }
    // K2b: mirror upper -> lower
    {
        dim3 grid(120 * 16, Bb);
        mirror_kernel<<<grid, 256>>>(out);
    }
    // K3/K4: symmetric softmax (row stats == col stats) + mask
    row_stats_kernel<<<ROWS, 256>>>(out);
    norm_mask_kernel<<<ROWS, 256>>>(out, mask);
}

// round 13
// speedup vs baseline: 2.0008x; 1.1438x over previous
#include <cuda_runtime.h>
#include <cuda_bf16.h>
#include <stdint.h>
#include <math.h>

#define Bb 8
#define Nn 2048
#define Dd 512
#define Pp 16
#define PH 512
#define ROWS (Bb*Nn)   // 16384
#define ESHIFT 40.0f

// ---------------- scratch ---------------------------------------------------
__device__ __nv_bfloat16 g_ctx_h[(size_t)ROWS * Dd];
__device__ __nv_bfloat16 g_ctx_l[(size_t)ROWS * Dd];
__device__ __nv_bfloat16 g_W_h[(size_t)PH * Dd];
__device__ __nv_bfloat16 g_W_l[(size_t)PH * Dd];
__device__ __nv_bfloat16 g_G_h[(size_t)ROWS * PH];
__device__ __nv_bfloat16 g_G_l[(size_t)ROWS * PH];
__device__ float g_sum[ROWS];    // per-row (== per-col) sum of E
__device__ float g_rinv[ROWS];

// ---------------- small PTX helpers (base-ISA only) ------------------------
__device__ __forceinline__ uint32_t smem_u32(const void* p) {
    uint32_t a;
    asm("{ .reg .u64 t; cvta.to.shared.u64 t, %1; cvt.u32.u64 %0, t; }" : "=r"(a) : "l"(p));
    return a;
}
__device__ __forceinline__ void cpa16(uint32_t saddr, const void* g) {
    asm volatile("cp.async.cg.shared.global [%0], [%1], 16;" :: "r"(saddr), "l"(g));
}
#define CP_COMMIT() asm volatile("cp.async.commit_group;" ::: "memory")
#define CP_WAIT(n)  asm volatile("cp.async.wait_group %0;" :: "n"(n) : "memory")

__device__ __forceinline__ void ldsm4(uint32_t& d0, uint32_t& d1, uint32_t& d2, uint32_t& d3,
                                      uint32_t addr) {
    asm volatile("ldmatrix.sync.aligned.m8n8.x4.shared.b16 {%0,%1,%2,%3}, [%4];"
                 : "=r"(d0), "=r"(d1), "=r"(d2), "=r"(d3) : "r"(addr));
}
__device__ __forceinline__ void mma_bf16(float* c, const uint32_t* a, uint32_t b0, uint32_t b1) {
    asm volatile("mma.sync.aligned.m16n8k16.row.col.f32.bf16.bf16.f32 "
                 "{%0,%1,%2,%3}, {%4,%5,%6,%7}, {%8,%9}, {%0,%1,%2,%3};"
                 : "+f"(c[0]), "+f"(c[1]), "+f"(c[2]), "+f"(c[3])
                 : "r"(a[0]), "r"(a[1]), "r"(a[2]), "r"(a[3]), "r"(b0), "r"(b1));
}

// ---------------- split fp32 -> (hi, lo) bf16 ------------------------------
__global__ __launch_bounds__(256)
void split_kernel(const float* __restrict__ x, __nv_bfloat16* __restrict__ h,
                  __nv_bfloat16* __restrict__ l, int n4)
{
    int i = blockIdx.x * blockDim.x + threadIdx.x;
    if (i >= n4) return;
    float4 v = ((const float4*)x)[i];
    __nv_bfloat16 h0 = __float2bfloat16(v.x), h1 = __float2bfloat16(v.y);
    __nv_bfloat16 h2 = __float2bfloat16(v.z), h3 = __float2bfloat16(v.w);
    __nv_bfloat16 l0 = __float2bfloat16(v.x - __bfloat162float(h0));
    __nv_bfloat16 l1 = __float2bfloat16(v.y - __bfloat162float(h1));
    __nv_bfloat16 l2 = __float2bfloat16(v.z - __bfloat162float(h2));
    __nv_bfloat16 l3 = __float2bfloat16(v.w - __bfloat162float(h3));
    __nv_bfloat162 hp0 = __halves2bfloat162(h0, h1), hp1 = __halves2bfloat162(h2, h3);
    __nv_bfloat162 lp0 = __halves2bfloat162(l0, l1), lp1 = __halves2bfloat162(l2, l3);
    uint2 hv, lv;
    hv.x = *(uint32_t*)&hp0; hv.y = *(uint32_t*)&hp1;
    lv.x = *(uint32_t*)&lp0; lv.y = *(uint32_t*)&lp1;
    ((uint2*)h)[i] = hv;
    ((uint2*)l)[i] = lv;
}

// ---------------- mma.sync GEMM, BK=64, 3-stage, 1 barrier/iter ------------
// 3 accumulation passes: Ahi·Bhi^T + Ahi·Blo^T + Alo·Bhi^T.
// EPI=0 (K2): store E = exp(alpha*acc - ESHIFT); accumulate row/col sums of E
//             into g_sum (symmetric Gram: col sums pushed as row sums of bj).
// EPI=1 (K1): relu + split into (Ch, Cl).
// SYM=1: blockIdx.x in [0,136) -> upper-triangular (bi<=bj) 128-block.
#define ROWB    144         // 64 bf16 (128B) + 16B pad
#define NIT     24          // 3 terms * (512/64)
#define MAT_B   18432       // 128*ROWB bytes per matrix tile
#define STAGE_B (2*MAT_B)   // A + B
#define GEMM_SMEM (3*STAGE_B)

template<int EPI, int SYM>
__global__ __launch_bounds__(256, 2)
void mma_gemm(const __nv_bfloat16* __restrict__ Ah, const __nv_bfloat16* __restrict__ Al,
              const __nv_bfloat16* __restrict__ Bh, const __nv_bfloat16* __restrict__ Bl,
              float* __restrict__ Cf, __nv_bfloat16* __restrict__ Ch, __nv_bfloat16* __restrict__ Cl,
              int Ncols, size_t sA, size_t sB, size_t sC, float alpha)
{
    extern __shared__ char dsm[];

    const int tid  = threadIdx.x;
    const int wid  = tid >> 5;
    const int lane = tid & 31;
    const int wm   = wid >> 2;        // 0..1  (M warp row, 64 rows)
    const int wn   = wid & 3;         // 0..3  (N warp col, 32 cols)

    int m0, n0;
    if (SYM) {
        int idx = blockIdx.x, bi = 0, bj = 0, off = 0;
#pragma unroll 1
        for (int i = 0; i < 16; i++) {
            int cnt = 16 - i;
            if (idx < off + cnt) { bi = i; bj = i + idx - off; break; }
            off += cnt;
        }
        m0 = bi * 128; n0 = bj * 128;
    } else {
        m0 = blockIdx.y * 128; n0 = blockIdx.x * 128;
    }

    const size_t zAb = (size_t)blockIdx.z * sA * 2;   // bytes
    const size_t zBb = (size_t)blockIdx.z * sB * 2;
    const size_t zC  = (size_t)blockIdx.z * sC;

    const int r0 = tid >> 3;
    const int c0 = tid & 7;
    const uint32_t s_off0 = (uint32_t)r0 * ROWB + (uint32_t)c0 * 16;
    const size_t   a_off0 = (size_t)(m0 + r0) * 1024 + (size_t)c0 * 16;
    const size_t   b_off0 = (size_t)(n0 + r0) * 1024 + (size_t)c0 * 16;

    uint32_t as_b[3], bs_b[3];
#pragma unroll
    for (int s = 0; s < 3; s++) {
        as_b[s] = smem_u32(dsm + s * STAGE_B);
        bs_b[s] = smem_u32(dsm + s * STAGE_B + MAT_B);
    }

    const char* Ahb = (const char*)Ah + zAb;
    const char* Alb = (const char*)Al + zAb;
    const char* Bhb = (const char*)Bh + zBb;
    const char* Blb = (const char*)Bl + zBb;

    float acc[4][4][4];
#pragma unroll
    for (int i = 0; i < 4; i++)
#pragma unroll
        for (int j = 0; j < 4; j++)
#pragma unroll
            for (int k = 0; k < 4; k++) acc[i][j][k] = 0.f;

    const int rA = wm * 64 + (lane & 15);
    const int rB = wn * 32 + (lane & 15);
    const uint32_t half16 = (uint32_t)(lane >> 4) * 16;

    auto prefetch = [&](int it, int buf) {
        const int term = it >> 3;
        const int kc   = it & 7;
        const char* Ab  = (term == 2) ? Alb : Ahb;
        const char* Bbp = (term == 1) ? Blb : Bhb;
        const size_t koff = (size_t)kc * 128;
        uint32_t sa = as_b[buf] + s_off0;
        uint32_t sb = bs_b[buf] + s_off0;
#pragma unroll
        for (int q = 0; q < 4; q++) {
            cpa16(sa + q * 32 * ROWB, Ab  + a_off0 + (size_t)(q * 32) * 1024 + koff);
            cpa16(sb + q * 32 * ROWB, Bbp + b_off0 + (size_t)(q * 32) * 1024 + koff);
        }
    };

    prefetch(0, 0); CP_COMMIT();
    prefetch(1, 1); CP_COMMIT();

#pragma unroll 3
    for (int it = 0; it < NIT; ++it) {
        const int buf = it % 3;
        if (it < NIT - 1) { CP_WAIT(1); } else { CP_WAIT(0); }
        __syncthreads();

#pragma unroll
        for (int ks = 0; ks < 4; ks++) {
            uint32_t a[4][4];
            uint32_t b[2][4];
#pragma unroll
            for (int mi = 0; mi < 4; mi++) {
                uint32_t addr = as_b[buf] + (uint32_t)(rA + mi * 16) * ROWB
                              + (uint32_t)ks * 32 + half16;
                ldsm4(a[mi][0], a[mi][1], a[mi][2], a[mi][3], addr);
            }
#pragma unroll
            for (int nb = 0; nb < 2; nb++) {
                uint32_t addr = bs_b[buf] + (uint32_t)(rB + nb * 16) * ROWB
                              + (uint32_t)ks * 32 + half16;
                ldsm4(b[nb][0], b[nb][1], b[nb][2], b[nb][3], addr);
            }
#pragma unroll
            for (int mi = 0; mi < 4; mi++)
#pragma unroll
                for (int g = 0; g < 4; g++)
                    mma_bf16(acc[mi][g], a[mi], b[g >> 1][g & 1], b[g >> 1][(g & 1) + 2]);
        }
        if (it + 2 < NIT) { prefetch(it + 2, (it + 2) % 3); CP_COMMIT(); }
    }

    // ---------------- epilogue ----------------
    const int er = m0 + wm * 64 + (lane >> 2);
    const int ec = n0 + wn * 32 + (lane & 3) * 2;

    if (EPI == 1) {
#pragma unroll
        for (int mi = 0; mi < 4; mi++)
#pragma unroll
            for (int g = 0; g < 4; g++) {
                const int r = er + mi * 16;
                const int c = ec + g * 8;
#pragma unroll
                for (int hrow = 0; hrow < 2; hrow++) {
                    float v0 = fmaxf(acc[mi][g][2 * hrow + 0], 0.f);
                    float v1 = fmaxf(acc[mi][g][2 * hrow + 1], 0.f);
                    __nv_bfloat16 h0 = __float2bfloat16(v0), h1 = __float2bfloat16(v1);
                    __nv_bfloat16 l0 = __float2bfloat16(v0 - __bfloat162float(h0));
                    __nv_bfloat16 l1 = __float2bfloat16(v1 - __bfloat162float(h1));
                    __nv_bfloat162 hp = __halves2bfloat162(h0, h1);
                    __nv_bfloat162 lp = __halves2bfloat162(l0, l1);
                    const size_t o = (size_t)(r + 8 * hrow) * Ncols + c;
                    *(uint32_t*)(Ch + o) = *(uint32_t*)&hp;
                    *(uint32_t*)(Cl + o) = *(uint32_t*)&lp;
                }
            }
    } else {
        // E = exp(alpha*acc - ESHIFT); store E; accumulate row/col sums.
        float e[4][4][4];
#pragma unroll
        for (int mi = 0; mi < 4; mi++)
#pragma unroll
            for (int g = 0; g < 4; g++)
#pragma unroll
                for (int k = 0; k < 4; k++)
                    e[mi][g][k] = __expf(fmaf(acc[mi][g][k], alpha, -ESHIFT));

        // stores
#pragma unroll
        for (int mi = 0; mi < 4; mi++)
#pragma unroll
            for (int g = 0; g < 4; g++) {
                const int r = er + mi * 16;
                const int c = ec + g * 8;
                *(float2*)(Cf + zC + (size_t)r * Ncols + c)       = make_float2(e[mi][g][0], e[mi][g][1]);
                *(float2*)(Cf + zC + (size_t)(r + 8) * Ncols + c) = make_float2(e[mi][g][2], e[mi][g][3]);
            }

        // smem reduction buffers (mainloop smem no longer needed)
        float* srow = (float*)dsm;        // [128]
        float* scol = srow + 128;         // [128]
        __syncthreads();
        if (tid < 128) { srow[tid] = 0.f; scol[tid] = 0.f; }
        __syncthreads();

        // row partials: row (mi,h) sum over this thread's 8 cols
#pragma unroll
        for (int mi = 0; mi < 4; mi++)
#pragma unroll
            for (int h = 0; h < 2; h++) {
                float rp = 0.f;
#pragma unroll
                for (int g = 0; g < 4; g++)
                    rp += e[mi][g][2 * h + 0] + e[mi][g][2 * h + 1];
                rp += __shfl_xor_sync(0xffffffffu, rp, 1);
                rp += __shfl_xor_sync(0xffffffffu, rp, 2);
                if ((lane & 3) == 0) {
                    int wr = wm * 64 + (lane >> 2) + mi * 16 + 8 * h;
                    atomicAdd(&srow[wr], rp);
                }
            }
        // col partials: col (g,p) sum over this thread's 8 rows
#pragma unroll
        for (int g = 0; g < 4; g++)
#pragma unroll
            for (int p = 0; p < 2; p++) {
                float cp = 0.f;
#pragma unroll
                for (int mi = 0; mi < 4; mi++)
                    cp += e[mi][g][p] + e[mi][g][2 + p];
                cp += __shfl_xor_sync(0xffffffffu, cp, 4);
                cp += __shfl_xor_sync(0xffffffffu, cp, 8);
                cp += __shfl_xor_sync(0xffffffffu, cp, 16);
                if (lane < 4) {
                    int wc = wn * 32 + (lane & 3) * 2 + 8 * g + p;
                    atomicAdd(&scol[wc], cp);
                }
            }
        __syncthreads();
        const size_t zS = (size_t)blockIdx.z * Nn;
        if (tid < 128) {
            atomicAdd(&g_sum[zS + m0 + tid], srow[tid]);
            if (m0 != n0) atomicAdd(&g_sum[zS + n0 + tid], scol[tid]);
        }
    }
}

// ---------------- tiny kernels: zero sums / invert sums --------------------
__global__ __launch_bounds__(256)
void zero_sums_kernel() {
    g_sum[blockIdx.x * 256 + threadIdx.x] = 0.f;
}
__global__ __launch_bounds__(256)
void inv_sums_kernel() {
    int i = blockIdx.x * 256 + threadIdx.x;
    g_rinv[i] = 1.f / g_sum[i];
}

// ---------------- fused mirror + normalize + mask --------------------------
// Processes upper-triangular 32x32 subtiles of E; writes normalized output
// to (m,n) and (for off-diagonal block pairs) transposed to (n,m).
// out[r][c] = E[r][c] * rinv[c] * mask[r] * mask[c]   (softmax over axis=1)
__global__ __launch_bounds__(256)
void norm_sym_kernel(float* __restrict__ S, const int* __restrict__ mask)
{
    __shared__ float t[32][33];
    const int pair = blockIdx.x >> 4;
    const int sub  = blockIdx.x & 15;
    const int b    = blockIdx.y;

    int bi = 0, bj = 0, off = 0;
#pragma unroll 1
    for (int i = 0; i < 16; i++) {
        int cnt = 16 - i;
        if (pair < off + cnt) { bi = i; bj = i + pair - off; break; }
        off += cnt;
    }
    const int m0 = bi * 128 + (sub >> 2) * 32;   // rows of stored tile
    const int n0 = bj * 128 + (sub & 3) * 32;    // cols of stored tile
    const size_t base = (size_t)b * Nn * Nn;
    const int zS = b * Nn;

    const int tx = threadIdx.x & 31;
    const int ty = threadIdx.x >> 5;             // 0..7

    const float rv_c = g_rinv[zS + n0 + tx];
    const float mk_c = (float)mask[zS + n0 + tx];

    // load E tile into smem, write direct-normalized output
#pragma unroll
    for (int j = 0; j < 32; j += 8) {
        float ev = S[base + (size_t)(m0 + ty + j) * Nn + n0 + tx];
        t[ty + j][tx] = ev;
        float mk_r = (float)mask[zS + m0 + ty + j];
        S[base + (size_t)(m0 + ty + j) * Nn + n0 + tx] = ev * rv_c * mk_r * mk_c;
    }
    if (bi == bj) return;                        // diagonal block: single write

    __syncthreads();
    // transposed write: out[n0+ty+j][m0+tx] = E^T * rinv[m0+tx] * masks
    const float rv_c2 = g_rinv[zS + m0 + tx];
    const float mk_c2 = (float)mask[zS + m0 + tx];
#pragma unroll
    for (int j = 0; j < 32; j += 8) {
        float ev = t[tx][ty + j];
        float mk_r = (float)mask[zS + n0 + ty + j];
        S[base + (size_t)(n0 + ty + j) * Nn + m0 + tx] = ev * rv_c2 * mk_r * mk_c2;
    }
}

// ---------------- launch ---------------------------------------------------
extern "C" void kernel_launch(void* const* d_in, const int* in_sizes, int n_in,
                              void* d_out, int out_size)
{
    const float* ctx  = (const float*)d_in[0];   // [8, 2048, 512]
    const float* W    = (const float*)d_in[1];   // [16, 32, 512]
    const int*   mask = (const int*)d_in[2];     // [8, 2048]
    float* out = (float*)d_out;                  // [8, 2048, 2048]

    void *p_ch, *p_cl, *p_wh, *p_wl, *p_gh, *p_gl;
    cudaGetSymbolAddress(&p_ch, g_ctx_h); cudaGetSymbolAddress(&p_cl, g_ctx_l);
    cudaGetSymbolAddress(&p_wh, g_W_h);   cudaGetSymbolAddress(&p_wl, g_W_l);
    cudaGetSymbolAddress(&p_gh, g_G_h);   cudaGetSymbolAddress(&p_gl, g_G_l);
    __nv_bfloat16* Ch = (__nv_bfloat16*)p_ch; __nv_bfloat16* Cl = (__nv_bfloat16*)p_cl;
    __nv_bfloat16* Wh = (__nv_bfloat16*)p_wh; __nv_bfloat16* Wl = (__nv_bfloat16*)p_wl;
    __nv_bfloat16* Gh = (__nv_bfloat16*)p_gh; __nv_bfloat16* Gl = (__nv_bfloat16*)p_gl;

    cudaFuncSetAttribute(mma_gemm<0,1>, cudaFuncAttributeMaxDynamicSharedMemorySize, GEMM_SMEM);
    cudaFuncSetAttribute(mma_gemm<1,0>, cudaFuncAttributeMaxDynamicSharedMemorySize, GEMM_SMEM);

    // K0: split inputs into hi/lo bf16; zero the softmax sums
    {
        int n4 = ROWS * Dd / 4;
        split_kernel<<<(n4 + 255) / 256, 256>>>(ctx, Ch, Cl, n4);
        int w4 = PH * Dd / 4;
        split_kernel<<<(w4 + 255) / 256, 256>>>(W, Wh, Wl, w4);
        zero_sums_kernel<<<ROWS / 256, 256>>>();
    }
    // K1: G = relu(ctx @ W^T) -> Gh/Gl bf16 split (fused epilogue)
    {
        dim3 grid(PH / 128, ROWS / 128, 1);
        mma_gemm<1,0><<<grid, 256, GEMM_SMEM>>>(Ch, Cl, Wh, Wl, nullptr, Gh, Gl,
                                                PH, 0, 0, 0, 1.0f);
    }
    // K2: E = exp(G·G^T/16 - 40) on upper-triangular blocks + row/col sums
    {
        dim3 grid(136, 1, Bb);
        mma_gemm<0,1><<<grid, 256, GEMM_SMEM>>>(Gh, Gl, Gh, Gl, out, nullptr, nullptr,
                                                Nn, (size_t)Nn * PH, (size_t)Nn * PH,
                                                (size_t)Nn * Nn, 1.0f / (float)Pp);
    }
    // K3: rinv = 1/sum
    inv_sums_kernel<<<ROWS / 256, 256>>>();
    // K4: fused mirror + normalize + mask
    {
        dim3 grid(136 * 16, Bb);
        norm_sym_kernel<<<grid, 256>>>(out, mask);
    }
}

// round 14
// speedup vs baseline: 2.0300x; 1.0146x over previous
#include <cuda_runtime.h>
#include <cuda_bf16.h>
#include <stdint.h>
#include <math.h>

#define Bb 8
#define Nn 2048
#define Dd 512
#define Pp 16
#define PH 512
#define ROWS (Bb*Nn)   // 16384
#define ESHIFT 40.0f
#define LOG2E 1.44269504f

// ---------------- scratch ---------------------------------------------------
__device__ __nv_bfloat16 g_ctx_h[(size_t)ROWS * Dd];
__device__ __nv_bfloat16 g_ctx_l[(size_t)ROWS * Dd];
__device__ __nv_bfloat16 g_W_h[(size_t)PH * Dd];
__device__ __nv_bfloat16 g_W_l[(size_t)PH * Dd];
__device__ __nv_bfloat16 g_G_h[(size_t)ROWS * PH];
__device__ __nv_bfloat16 g_G_l[(size_t)ROWS * PH];
__device__ float g_sum[ROWS];    // per-row (== per-col) sum of E

// ---------------- small PTX helpers (base-ISA only) ------------------------
__device__ __forceinline__ uint32_t smem_u32(const void* p) {
    uint32_t a;
    asm("{ .reg .u64 t; cvta.to.shared.u64 t, %1; cvt.u32.u64 %0, t; }" : "=r"(a) : "l"(p));
    return a;
}
__device__ __forceinline__ void cpa16(uint32_t saddr, const void* g) {
    asm volatile("cp.async.cg.shared.global [%0], [%1], 16;" :: "r"(saddr), "l"(g));
}
#define CP_COMMIT() asm volatile("cp.async.commit_group;" ::: "memory")
#define CP_WAIT(n)  asm volatile("cp.async.wait_group %0;" :: "n"(n) : "memory")

__device__ __forceinline__ void ldsm4(uint32_t& d0, uint32_t& d1, uint32_t& d2, uint32_t& d3,
                                      uint32_t addr) {
    asm volatile("ldmatrix.sync.aligned.m8n8.x4.shared.b16 {%0,%1,%2,%3}, [%4];"
                 : "=r"(d0), "=r"(d1), "=r"(d2), "=r"(d3) : "r"(addr));
}
__device__ __forceinline__ void mma_bf16(float* c, const uint32_t* a, uint32_t b0, uint32_t b1) {
    asm volatile("mma.sync.aligned.m16n8k16.row.col.f32.bf16.bf16.f32 "
                 "{%0,%1,%2,%3}, {%4,%5,%6,%7}, {%8,%9}, {%0,%1,%2,%3};"
                 : "+f"(c[0]), "+f"(c[1]), "+f"(c[2]), "+f"(c[3])
                 : "r"(a[0]), "r"(a[1]), "r"(a[2]), "r"(a[3]), "r"(b0), "r"(b1));
}

// ---------------- split fp32 -> (hi, lo) bf16 ------------------------------
__global__ __launch_bounds__(256)
void split_kernel(const float* __restrict__ x, __nv_bfloat16* __restrict__ h,
                  __nv_bfloat16* __restrict__ l, int n4)
{
    int i = blockIdx.x * blockDim.x + threadIdx.x;
    if (i >= n4) return;
    float4 v = ((const float4*)x)[i];
    __nv_bfloat16 h0 = __float2bfloat16(v.x), h1 = __float2bfloat16(v.y);
    __nv_bfloat16 h2 = __float2bfloat16(v.z), h3 = __float2bfloat16(v.w);
    __nv_bfloat16 l0 = __float2bfloat16(v.x - __bfloat162float(h0));
    __nv_bfloat16 l1 = __float2bfloat16(v.y - __bfloat162float(h1));
    __nv_bfloat16 l2 = __float2bfloat16(v.z - __bfloat162float(h2));
    __nv_bfloat16 l3 = __float2bfloat16(v.w - __bfloat162float(h3));
    __nv_bfloat162 hp0 = __halves2bfloat162(h0, h1), hp1 = __halves2bfloat162(h2, h3);
    __nv_bfloat162 lp0 = __halves2bfloat162(l0, l1), lp1 = __halves2bfloat162(l2, l3);
    uint2 hv, lv;
    hv.x = *(uint32_t*)&hp0; hv.y = *(uint32_t*)&hp1;
    lv.x = *(uint32_t*)&lp0; lv.y = *(uint32_t*)&lp1;
    ((uint2*)h)[i] = hv;
    ((uint2*)l)[i] = lv;
}

// ---------------- mma.sync GEMM, BK=64, 3-stage, 1 barrier/iter ------------
// 3 accumulation passes: Ahi·Bhi^T + Ahi·Blo^T + Alo·Bhi^T.
// EPI=0 (K2): store E = exp2(acc*alpha*log2e - 40*log2e); accumulate row/col
//             sums of E into g_sum (symmetric Gram: col sums -> rows of bj).
// EPI=1 (K1): relu + split into (Ch, Cl).
// SYM=1: blockIdx.x in [0,136) -> upper-triangular (bi<=bj) 128-block.
#define ROWB    144         // 64 bf16 (128B) + 16B pad
#define NIT     24          // 3 terms * (512/64)
#define MAT_B   18432       // 128*ROWB bytes per matrix tile
#define STAGE_B (2*MAT_B)   // A + B
#define GEMM_SMEM (3*STAGE_B)

template<int EPI, int SYM>
__global__ __launch_bounds__(256, 2)
void mma_gemm(const __nv_bfloat16* __restrict__ Ah, const __nv_bfloat16* __restrict__ Al,
              const __nv_bfloat16* __restrict__ Bh, const __nv_bfloat16* __restrict__ Bl,
              float* __restrict__ Cf, __nv_bfloat16* __restrict__ Ch, __nv_bfloat16* __restrict__ Cl,
              int Ncols, size_t sA, size_t sB, size_t sC, float alpha)
{
    extern __shared__ char dsm[];

    const int tid  = threadIdx.x;
    const int wid  = tid >> 5;
    const int lane = tid & 31;
    const int wm   = wid >> 2;        // 0..1  (M warp row, 64 rows)
    const int wn   = wid & 3;         // 0..3  (N warp col, 32 cols)

    int m0, n0;
    if (SYM) {
        int idx = blockIdx.x, bi = 0, bj = 0, off = 0;
#pragma unroll 1
        for (int i = 0; i < 16; i++) {
            int cnt = 16 - i;
            if (idx < off + cnt) { bi = i; bj = i + idx - off; break; }
            off += cnt;
        }
        m0 = bi * 128; n0 = bj * 128;
    } else {
        m0 = blockIdx.y * 128; n0 = blockIdx.x * 128;
    }

    const size_t zAb = (size_t)blockIdx.z * sA * 2;   // bytes
    const size_t zBb = (size_t)blockIdx.z * sB * 2;
    const size_t zC  = (size_t)blockIdx.z * sC;

    const int r0 = tid >> 3;
    const int c0 = tid & 7;
    const uint32_t s_off0 = (uint32_t)r0 * ROWB + (uint32_t)c0 * 16;
    const size_t   a_off0 = (size_t)(m0 + r0) * 1024 + (size_t)c0 * 16;
    const size_t   b_off0 = (size_t)(n0 + r0) * 1024 + (size_t)c0 * 16;

    uint32_t as_b[3], bs_b[3];
#pragma unroll
    for (int s = 0; s < 3; s++) {
        as_b[s] = smem_u32(dsm + s * STAGE_B);
        bs_b[s] = smem_u32(dsm + s * STAGE_B + MAT_B);
    }

    const char* Ahb = (const char*)Ah + zAb;
    const char* Alb = (const char*)Al + zAb;
    const char* Bhb = (const char*)Bh + zBb;
    const char* Blb = (const char*)Bl + zBb;

    float acc[4][4][4];
#pragma unroll
    for (int i = 0; i < 4; i++)
#pragma unroll
        for (int j = 0; j < 4; j++)
#pragma unroll
            for (int k = 0; k < 4; k++) acc[i][j][k] = 0.f;

    const int rA = wm * 64 + (lane & 15);
    const int rB = wn * 32 + (lane & 15);
    const uint32_t half16 = (uint32_t)(lane >> 4) * 16;

    auto prefetch = [&](int it, int buf) {
        const int term = it >> 3;
        const int kc   = it & 7;
        const char* Ab  = (term == 2) ? Alb : Ahb;
        const char* Bbp = (term == 1) ? Blb : Bhb;
        const size_t koff = (size_t)kc * 128;
        uint32_t sa = as_b[buf] + s_off0;
        uint32_t sb = bs_b[buf] + s_off0;
#pragma unroll
        for (int q = 0; q < 4; q++) {
            cpa16(sa + q * 32 * ROWB, Ab  + a_off0 + (size_t)(q * 32) * 1024 + koff);
            cpa16(sb + q * 32 * ROWB, Bbp + b_off0 + (size_t)(q * 32) * 1024 + koff);
        }
    };

    prefetch(0, 0); CP_COMMIT();
    prefetch(1, 1); CP_COMMIT();

#pragma unroll 3
    for (int it = 0; it < NIT; ++it) {
        const int buf = it % 3;
        if (it < NIT - 1) { CP_WAIT(1); } else { CP_WAIT(0); }
        __syncthreads();

#pragma unroll
        for (int ks = 0; ks < 4; ks++) {
            uint32_t a[4][4];
            uint32_t b[2][4];
#pragma unroll
            for (int mi = 0; mi < 4; mi++) {
                uint32_t addr = as_b[buf] + (uint32_t)(rA + mi * 16) * ROWB
                              + (uint32_t)ks * 32 + half16;
                ldsm4(a[mi][0], a[mi][1], a[mi][2], a[mi][3], addr);
            }
#pragma unroll
            for (int nb = 0; nb < 2; nb++) {
                uint32_t addr = bs_b[buf] + (uint32_t)(rB + nb * 16) * ROWB
                              + (uint32_t)ks * 32 + half16;
                ldsm4(b[nb][0], b[nb][1], b[nb][2], b[nb][3], addr);
            }
#pragma unroll
            for (int mi = 0; mi < 4; mi++)
#pragma unroll
                for (int g = 0; g < 4; g++)
                    mma_bf16(acc[mi][g], a[mi], b[g >> 1][g & 1], b[g >> 1][(g & 1) + 2]);
        }
        if (it + 2 < NIT) { prefetch(it + 2, (it + 2) % 3); CP_COMMIT(); }
    }

    // ---------------- epilogue ----------------
    const int er = m0 + wm * 64 + (lane >> 2);
    const int ec = n0 + wn * 32 + (lane & 3) * 2;

    if (EPI == 1) {
#pragma unroll
        for (int mi = 0; mi < 4; mi++)
#pragma unroll
            for (int g = 0; g < 4; g++) {
                const int r = er + mi * 16;
                const int c = ec + g * 8;
#pragma unroll
                for (int hrow = 0; hrow < 2; hrow++) {
                    float v0 = fmaxf(acc[mi][g][2 * hrow + 0], 0.f);
                    float v1 = fmaxf(acc[mi][g][2 * hrow + 1], 0.f);
                    __nv_bfloat16 h0 = __float2bfloat16(v0), h1 = __float2bfloat16(v1);
                    __nv_bfloat16 l0 = __float2bfloat16(v0 - __bfloat162float(h0));
                    __nv_bfloat16 l1 = __float2bfloat16(v1 - __bfloat162float(h1));
                    __nv_bfloat162 hp = __halves2bfloat162(h0, h1);
                    __nv_bfloat162 lp = __halves2bfloat162(l0, l1);
                    const size_t o = (size_t)(r + 8 * hrow) * Ncols + c;
                    *(uint32_t*)(Ch + o) = *(uint32_t*)&hp;
                    *(uint32_t*)(Cl + o) = *(uint32_t*)&lp;
                }
            }
    } else {
        // E = exp2(acc*a2 - s2); store E; accumulate row/col sums.
        const float a2 = alpha * LOG2E;
        const float s2 = ESHIFT * LOG2E;
        float e[4][4][4];
#pragma unroll
        for (int mi = 0; mi < 4; mi++)
#pragma unroll
            for (int g = 0; g < 4; g++)
#pragma unroll
                for (int k = 0; k < 4; k++)
                    e[mi][g][k] = exp2f(fmaf(acc[mi][g][k], a2, -s2));

#pragma unroll
        for (int mi = 0; mi < 4; mi++)
#pragma unroll
            for (int g = 0; g < 4; g++) {
                const int r = er + mi * 16;
                const int c = ec + g * 8;
                *(float2*)(Cf + zC + (size_t)r * Ncols + c)       = make_float2(e[mi][g][0], e[mi][g][1]);
                *(float2*)(Cf + zC + (size_t)(r + 8) * Ncols + c) = make_float2(e[mi][g][2], e[mi][g][3]);
            }

        float* srow = (float*)dsm;        // [128]
        float* scol = srow + 128;         // [128]
        __syncthreads();
        if (tid < 128) { srow[tid] = 0.f; scol[tid] = 0.f; }
        __syncthreads();

#pragma unroll
        for (int mi = 0; mi < 4; mi++)
#pragma unroll
            for (int h = 0; h < 2; h++) {
                float rp = 0.f;
#pragma unroll
                for (int g = 0; g < 4; g++)
                    rp += e[mi][g][2 * h + 0] + e[mi][g][2 * h + 1];
                rp += __shfl_xor_sync(0xffffffffu, rp, 1);
                rp += __shfl_xor_sync(0xffffffffu, rp, 2);
                if ((lane & 3) == 0) {
                    int wr = wm * 64 + (lane >> 2) + mi * 16 + 8 * h;
                    atomicAdd(&srow[wr], rp);
                }
            }
#pragma unroll
        for (int g = 0; g < 4; g++)
#pragma unroll
            for (int p = 0; p < 2; p++) {
                float cp = 0.f;
#pragma unroll
                for (int mi = 0; mi < 4; mi++)
                    cp += e[mi][g][p] + e[mi][g][2 + p];
                cp += __shfl_xor_sync(0xffffffffu, cp, 4);
                cp += __shfl_xor_sync(0xffffffffu, cp, 8);
                cp += __shfl_xor_sync(0xffffffffu, cp, 16);
                if (lane < 4) {
                    int wc = wn * 32 + (lane & 3) * 2 + 8 * g + p;
                    atomicAdd(&scol[wc], cp);
                }
            }
        __syncthreads();
        const size_t zS = (size_t)blockIdx.z * Nn;
        if (tid < 128) {
            atomicAdd(&g_sum[zS + m0 + tid], srow[tid]);
            if (m0 != n0) atomicAdd(&g_sum[zS + n0 + tid], scol[tid]);
        }
    }
}

// ---------------- tiny kernel: zero sums -----------------------------------
__global__ __launch_bounds__(256)
void zero_sums_kernel() {
    g_sum[blockIdx.x * 256 + threadIdx.x] = 0.f;
}

// ---------------- fused mirror + normalize + mask (float4) -----------------
// Each block handles a 32x128 strip of an upper-triangular 128-block (bi,bj):
// direct-normalized write of the strip, plus (bi!=bj) the transposed 128x32
// region. rinv computed inline from g_sum.
// out[r][c] = E[r][c] / sum[c] * mask[r] * mask[c]   (softmax over axis=1)
__global__ __launch_bounds__(256)
void norm_sym_kernel(float* __restrict__ S, const int* __restrict__ mask)
{
    __shared__ float sm[32][129];
    const int strip = blockIdx.x & 3;
    const int pair  = blockIdx.x >> 2;   // 0..135
    const int b     = blockIdx.y;

    int bi = 0, bj = 0, off = 0;
#pragma unroll 1
    for (int i = 0; i < 16; i++) {
        int cnt = 16 - i;
        if (pair < off + cnt) { bi = i; bj = i + pair - off; break; }
        off += cnt;
    }
    const int m0 = bi * 128 + strip * 32;   // strip rows
    const int n0 = bj * 128;                // full 128 cols
    const size_t base = (size_t)b * Nn * Nn;
    const int zS = b * Nn;

    const int t    = threadIdx.x;
    const int col4 = t & 31;                // float4 column (const across q)
    const int row0 = t >> 5;                // 0..7

    // column factors for direct pass: 1/sum * mask, 4 cols
    float4 sum4 = *(const float4*)(g_sum + zS + n0 + col4 * 4);
    int4   mi4  = *(const int4*)(mask + zS + n0 + col4 * 4);
    float4 c4;
    c4.x = (1.0f / sum4.x) * (float)mi4.x;
    c4.y = (1.0f / sum4.y) * (float)mi4.y;
    c4.z = (1.0f / sum4.z) * (float)mi4.z;
    c4.w = (1.0f / sum4.w) * (float)mi4.w;

#pragma unroll
    for (int q = 0; q < 4; q++) {
        const int row = row0 + 8 * q;
        const size_t go = base + (size_t)(m0 + row) * Nn + n0 + col4 * 4;
        float4 ev = *(const float4*)(S + go);
        sm[row][col4 * 4 + 0] = ev.x;
        sm[row][col4 * 4 + 1] = ev.y;
        sm[row][col4 * 4 + 2] = ev.z;
        sm[row][col4 * 4 + 3] = ev.w;
        const float mr = (float)mask[zS + m0 + row];
        float4 o;
        o.x = ev.x * c4.x * mr; o.y = ev.y * c4.y * mr;
        o.z = ev.z * c4.z * mr; o.w = ev.w * c4.w * mr;
        *(float4*)(S + go) = o;
    }
    if (bi == bj) return;                   // diag 128-block fully stored by K2

    __syncthreads();
    // transposed region: rows n0..n0+128, cols m0..m0+32 (8 float4 per row)
    const int col4t = t & 7;                // const across q
    const int rbase = t >> 3;               // 0..31
    float4 sum4b = *(const float4*)(g_sum + zS + m0 + col4t * 4);
    int4   mi4b  = *(const int4*)(mask + zS + m0 + col4t * 4);
    float4 c4b;
    c4b.x = (1.0f / sum4b.x) * (float)mi4b.x;
    c4b.y = (1.0f / sum4b.y) * (float)mi4b.y;
    c4b.z = (1.0f / sum4b.z) * (float)mi4b.z;
    c4b.w = (1.0f / sum4b.w) * (float)mi4b.w;

#pragma unroll
    for (int q = 0; q < 4; q++) {
        const int rw = rbase + 32 * q;      // 0..127: row within transposed region
        // conflict-free gather: bank = (4*col4t + k + rw) mod 32 distinct per lane
        float4 v;
        v.x = sm[col4t * 4 + 0][rw];
        v.y = sm[col4t * 4 + 1][rw];
        v.z = sm[col4t * 4 + 2][rw];
        v.w = sm[col4t * 4 + 3][rw];
        const float mr = (float)mask[zS + n0 + rw];
        float4 o;
        o.x = v.x * c4b.x * mr; o.y = v.y * c4b.y * mr;
        o.z = v.z * c4b.z * mr; o.w = v.w * c4b.w * mr;
        *(float4*)(S + base + (size_t)(n0 + rw) * Nn + m0 + col4t * 4) = o;
    }
}

// ---------------- launch ---------------------------------------------------
extern "C" void kernel_launch(void* const* d_in, const int* in_sizes, int n_in,
                              void* d_out, int out_size)
{
    const float* ctx  = (const float*)d_in[0];   // [8, 2048, 512]
    const float* W    = (const float*)d_in[1];   // [16, 32, 512]
    const int*   mask = (const int*)d_in[2];     // [8, 2048]
    float* out = (float*)d_out;                  // [8, 2048, 2048]

    void *p_ch, *p_cl, *p_wh, *p_wl, *p_gh, *p_gl;
    cudaGetSymbolAddress(&p_ch, g_ctx_h); cudaGetSymbolAddress(&p_cl, g_ctx_l);
    cudaGetSymbolAddress(&p_wh, g_W_h);   cudaGetSymbolAddress(&p_wl, g_W_l);
    cudaGetSymbolAddress(&p_gh, g_G_h);   cudaGetSymbolAddress(&p_gl, g_G_l);
    __nv_bfloat16* Ch = (__nv_bfloat16*)p_ch; __nv_bfloat16* Cl = (__nv_bfloat16*)p_cl;
    __nv_bfloat16* Wh = (__nv_bfloat16*)p_wh; __nv_bfloat16* Wl = (__nv_bfloat16*)p_wl;
    __nv_bfloat16* Gh = (__nv_bfloat16*)p_gh; __nv_bfloat16* Gl = (__nv_bfloat16*)p_gl;

    cudaFuncSetAttribute(mma_gemm<0,1>, cudaFuncAttributeMaxDynamicSharedMemorySize, GEMM_SMEM);
    cudaFuncSetAttribute(mma_gemm<1,0>, cudaFuncAttributeMaxDynamicSharedMemorySize, GEMM_SMEM);

    // K0: split inputs into hi/lo bf16; zero the softmax sums
    {
        int n4 = ROWS * Dd / 4;
        split_kernel<<<(n4 + 255) / 256, 256>>>(ctx, Ch, Cl, n4);
        int w4 = PH * Dd / 4;
        split_kernel<<<(w4 + 255) / 256, 256>>>(W, Wh, Wl, w4);
        zero_sums_kernel<<<ROWS / 256, 256>>>();
    }
    // K1: G = relu(ctx @ W^T) -> Gh/Gl bf16 split (fused epilogue)
    {
        dim3 grid(PH / 128, ROWS / 128, 1);
        mma_gemm<1,0><<<grid, 256, GEMM_SMEM>>>(Ch, Cl, Wh, Wl, nullptr, Gh, Gl,
                                                PH, 0, 0, 0, 1.0f);
    }
    // K2: E = exp(G·G^T/16 - 40) on upper-triangular blocks + row/col sums
    {
        dim3 grid(136, 1, Bb);
        mma_gemm<0,1><<<grid, 256, GEMM_SMEM>>>(Gh, Gl, Gh, Gl, out, nullptr, nullptr,
                                                Nn, (size_t)Nn * PH, (size_t)Nn * PH,
                                                (size_t)Nn * Nn, 1.0f / (float)Pp);
    }
    // K3: fused mirror + normalize + mask (rinv inline)
    {
        dim3 grid(136 * 4, Bb);
        norm_sym_kernel<<<grid, 256>>>(out, mask);
    }
}

// round 15
// speedup vs baseline: 2.0736x; 1.0215x over previous
#include <cuda_runtime.h>
#include <cuda_bf16.h>
#include <stdint.h>
#include <math.h>

#define Bb 8
#define Nn 2048
#define Dd 512
#define Pp 16
#define PH 512
#define ROWS (Bb*Nn)   // 16384
#define ESHIFT 40.0f
#define LOG2E 1.44269504f

// ---------------- scratch ---------------------------------------------------
__device__ __nv_bfloat16 g_ctx_h[(size_t)ROWS * Dd];
__device__ __nv_bfloat16 g_ctx_l[(size_t)ROWS * Dd];
__device__ __nv_bfloat16 g_W_h[(size_t)PH * Dd];
__device__ __nv_bfloat16 g_W_l[(size_t)PH * Dd];
__device__ __nv_bfloat16 g_G_h[(size_t)ROWS * PH];
__device__ __nv_bfloat16 g_G_l[(size_t)ROWS * PH];
__device__ float g_sum[ROWS];    // per-row (== per-col) sum of E

// ---------------- small PTX helpers (base-ISA only) ------------------------
__device__ __forceinline__ uint32_t smem_u32(const void* p) {
    uint32_t a;
    asm("{ .reg .u64 t; cvta.to.shared.u64 t, %1; cvt.u32.u64 %0, t; }" : "=r"(a) : "l"(p));
    return a;
}
__device__ __forceinline__ void cpa16(uint32_t saddr, const void* g) {
    asm volatile("cp.async.cg.shared.global [%0], [%1], 16;" :: "r"(saddr), "l"(g));
}
#define CP_COMMIT() asm volatile("cp.async.commit_group;" ::: "memory")
#define CP_WAIT(n)  asm volatile("cp.async.wait_group %0;" :: "n"(n) : "memory")

__device__ __forceinline__ void ldsm4(uint32_t& d0, uint32_t& d1, uint32_t& d2, uint32_t& d3,
                                      uint32_t addr) {
    asm volatile("ldmatrix.sync.aligned.m8n8.x4.shared.b16 {%0,%1,%2,%3}, [%4];"
                 : "=r"(d0), "=r"(d1), "=r"(d2), "=r"(d3) : "r"(addr));
}
__device__ __forceinline__ void mma_bf16(float* c, const uint32_t* a, uint32_t b0, uint32_t b1) {
    asm volatile("mma.sync.aligned.m16n8k16.row.col.f32.bf16.bf16.f32 "
                 "{%0,%1,%2,%3}, {%4,%5,%6,%7}, {%8,%9}, {%0,%1,%2,%3};"
                 : "+f"(c[0]), "+f"(c[1]), "+f"(c[2]), "+f"(c[3])
                 : "r"(a[0]), "r"(a[1]), "r"(a[2]), "r"(a[3]), "r"(b0), "r"(b1));
}

// ---------------- split fp32 -> (hi, lo) bf16 ------------------------------
// ZERO=1: threads with i < ROWS also zero g_sum[i] (fused zero_sums).
template<int ZERO>
__global__ __launch_bounds__(256)
void split_kernel(const float* __restrict__ x, __nv_bfloat16* __restrict__ h,
                  __nv_bfloat16* __restrict__ l, int n4)
{
    int i = blockIdx.x * blockDim.x + threadIdx.x;
    if (i >= n4) return;
    if (ZERO && i < ROWS) g_sum[i] = 0.f;
    float4 v = ((const float4*)x)[i];
    __nv_bfloat16 h0 = __float2bfloat16(v.x), h1 = __float2bfloat16(v.y);
    __nv_bfloat16 h2 = __float2bfloat16(v.z), h3 = __float2bfloat16(v.w);
    __nv_bfloat16 l0 = __float2bfloat16(v.x - __bfloat162float(h0));
    __nv_bfloat16 l1 = __float2bfloat16(v.y - __bfloat162float(h1));
    __nv_bfloat16 l2 = __float2bfloat16(v.z - __bfloat162float(h2));
    __nv_bfloat16 l3 = __float2bfloat16(v.w - __bfloat162float(h3));
    __nv_bfloat162 hp0 = __halves2bfloat162(h0, h1), hp1 = __halves2bfloat162(h2, h3);
    __nv_bfloat162 lp0 = __halves2bfloat162(l0, l1), lp1 = __halves2bfloat162(l2, l3);
    uint2 hv, lv;
    hv.x = *(uint32_t*)&hp0; hv.y = *(uint32_t*)&hp1;
    lv.x = *(uint32_t*)&lp0; lv.y = *(uint32_t*)&lp1;
    ((uint2*)h)[i] = hv;
    ((uint2*)l)[i] = lv;
}

// ---------------- mma.sync GEMM, BK=64, 3-stage, 1 barrier/iter ------------
// 3 accumulation passes: Ahi·Bhi^T + Ahi·Blo^T + Alo·Bhi^T.
// EPI=0 (K2): store E = exp2(acc*alpha*log2e - 40*log2e); accumulate row/col
//             sums of E into g_sum (symmetric Gram: col sums -> rows of bj).
// EPI=1 (K1): relu + split into (Ch, Cl).
// SYM=1: blockIdx.x in [0,136) -> upper-triangular (bi<=bj) 128-block.
#define ROWB    144         // 64 bf16 (128B) + 16B pad
#define NIT     24          // 3 terms * (512/64)
#define MAT_B   18432       // 128*ROWB bytes per matrix tile
#define STAGE_B (2*MAT_B)   // A + B
#define GEMM_SMEM (3*STAGE_B + 1024)

template<int EPI, int SYM>
__global__ __launch_bounds__(256, 2)
void mma_gemm(const __nv_bfloat16* __restrict__ Ah, const __nv_bfloat16* __restrict__ Al,
              const __nv_bfloat16* __restrict__ Bh, const __nv_bfloat16* __restrict__ Bl,
              float* __restrict__ Cf, __nv_bfloat16* __restrict__ Ch, __nv_bfloat16* __restrict__ Cl,
              int Ncols, size_t sA, size_t sB, size_t sC, float alpha)
{
    extern __shared__ char dsm[];

    const int tid  = threadIdx.x;
    const int wid  = tid >> 5;
    const int lane = tid & 31;
    const int wm   = wid >> 2;        // 0..1  (M warp row, 64 rows)
    const int wn   = wid & 3;         // 0..3  (N warp col, 32 cols)

    int m0, n0;
    if (SYM) {
        int idx = blockIdx.x, bi = 0, bj = 0, off = 0;
#pragma unroll 1
        for (int i = 0; i < 16; i++) {
            int cnt = 16 - i;
            if (idx < off + cnt) { bi = i; bj = i + idx - off; break; }
            off += cnt;
        }
        m0 = bi * 128; n0 = bj * 128;
    } else {
        m0 = blockIdx.y * 128; n0 = blockIdx.x * 128;
    }

    const size_t zAb = (size_t)blockIdx.z * sA * 2;   // bytes
    const size_t zBb = (size_t)blockIdx.z * sB * 2;
    const size_t zC  = (size_t)blockIdx.z * sC;

    const int r0 = tid >> 3;
    const int c0 = tid & 7;
    const uint32_t s_off0 = (uint32_t)r0 * ROWB + (uint32_t)c0 * 16;
    const size_t   a_off0 = (size_t)(m0 + r0) * 1024 + (size_t)c0 * 16;
    const size_t   b_off0 = (size_t)(n0 + r0) * 1024 + (size_t)c0 * 16;

    uint32_t as_b[3], bs_b[3];
#pragma unroll
    for (int s = 0; s < 3; s++) {
        as_b[s] = smem_u32(dsm + s * STAGE_B);
        bs_b[s] = smem_u32(dsm + s * STAGE_B + MAT_B);
    }

    const char* Ahb = (const char*)Ah + zAb;
    const char* Alb = (const char*)Al + zAb;
    const char* Bhb = (const char*)Bh + zBb;
    const char* Blb = (const char*)Bl + zBb;

    float acc[4][4][4];
#pragma unroll
    for (int i = 0; i < 4; i++)
#pragma unroll
        for (int j = 0; j < 4; j++)
#pragma unroll
            for (int k = 0; k < 4; k++) acc[i][j][k] = 0.f;

    const int rA = wm * 64 + (lane & 15);
    const int rB = wn * 32 + (lane & 15);
    const uint32_t half16 = (uint32_t)(lane >> 4) * 16;

    auto prefetch = [&](int it, int buf) {
        const int term = it >> 3;
        const int kc   = it & 7;
        const char* Ab  = (term == 2) ? Alb : Ahb;
        const char* Bbp = (term == 1) ? Blb : Bhb;
        const size_t koff = (size_t)kc * 128;
        uint32_t sa = as_b[buf] + s_off0;
        uint32_t sb = bs_b[buf] + s_off0;
#pragma unroll
        for (int q = 0; q < 4; q++) {
            cpa16(sa + q * 32 * ROWB, Ab  + a_off0 + (size_t)(q * 32) * 1024 + koff);
            cpa16(sb + q * 32 * ROWB, Bbp + b_off0 + (size_t)(q * 32) * 1024 + koff);
        }
    };

    prefetch(0, 0); CP_COMMIT();
    prefetch(1, 1); CP_COMMIT();

#pragma unroll 6
    for (int it = 0; it < NIT; ++it) {
        const int buf = it % 3;               // compile-time under unroll-6
        if (it < NIT - 1) { CP_WAIT(1); } else { CP_WAIT(0); }
        __syncthreads();

#pragma unroll
        for (int ks = 0; ks < 4; ks++) {
            uint32_t a[4][4];
            uint32_t b[2][4];
#pragma unroll
            for (int mi = 0; mi < 4; mi++) {
                uint32_t addr = as_b[buf] + (uint32_t)(rA + mi * 16) * ROWB
                              + (uint32_t)ks * 32 + half16;
                ldsm4(a[mi][0], a[mi][1], a[mi][2], a[mi][3], addr);
            }
#pragma unroll
            for (int nb = 0; nb < 2; nb++) {
                uint32_t addr = bs_b[buf] + (uint32_t)(rB + nb * 16) * ROWB
                              + (uint32_t)ks * 32 + half16;
                ldsm4(b[nb][0], b[nb][1], b[nb][2], b[nb][3], addr);
            }
#pragma unroll
            for (int mi = 0; mi < 4; mi++)
#pragma unroll
                for (int g = 0; g < 4; g++)
                    mma_bf16(acc[mi][g], a[mi], b[g >> 1][g & 1], b[g >> 1][(g & 1) + 2]);
        }
        if (it + 2 < NIT) { prefetch(it + 2, (it + 2) % 3); CP_COMMIT(); }
    }

    // ---------------- epilogue ----------------
    const int er = m0 + wm * 64 + (lane >> 2);
    const int ec = n0 + wn * 32 + (lane & 3) * 2;

    if (EPI == 1) {
#pragma unroll
        for (int mi = 0; mi < 4; mi++)
#pragma unroll
            for (int g = 0; g < 4; g++) {
                const int r = er + mi * 16;
                const int c = ec + g * 8;
#pragma unroll
                for (int hrow = 0; hrow < 2; hrow++) {
                    float v0 = fmaxf(acc[mi][g][2 * hrow + 0], 0.f);
                    float v1 = fmaxf(acc[mi][g][2 * hrow + 1], 0.f);
                    __nv_bfloat16 h0 = __float2bfloat16(v0), h1 = __float2bfloat16(v1);
                    __nv_bfloat16 l0 = __float2bfloat16(v0 - __bfloat162float(h0));
                    __nv_bfloat16 l1 = __float2bfloat16(v1 - __bfloat162float(h1));
                    __nv_bfloat162 hp = __halves2bfloat162(h0, h1);
                    __nv_bfloat162 lp = __halves2bfloat162(l0, l1);
                    const size_t o = (size_t)(r + 8 * hrow) * Ncols + c;
                    *(uint32_t*)(Ch + o) = *(uint32_t*)&hp;
                    *(uint32_t*)(Cl + o) = *(uint32_t*)&lp;
                }
            }
    } else {
        // E = exp2(acc*a2 - s2) computed IN-PLACE into acc; store; reduce.
        const float a2 = alpha * LOG2E;
        const float s2 = ESHIFT * LOG2E;
#pragma unroll
        for (int mi = 0; mi < 4; mi++)
#pragma unroll
            for (int g = 0; g < 4; g++)
#pragma unroll
                for (int k = 0; k < 4; k++)
                    acc[mi][g][k] = exp2f(fmaf(acc[mi][g][k], a2, -s2));

#pragma unroll
        for (int mi = 0; mi < 4; mi++)
#pragma unroll
            for (int g = 0; g < 4; g++) {
                const int r = er + mi * 16;
                const int c = ec + g * 8;
                *(float2*)(Cf + zC + (size_t)r * Ncols + c)       = make_float2(acc[mi][g][0], acc[mi][g][1]);
                *(float2*)(Cf + zC + (size_t)(r + 8) * Ncols + c) = make_float2(acc[mi][g][2], acc[mi][g][3]);
            }

        float* srow = (float*)(dsm + 3 * STAGE_B);   // [128] dedicated region
        float* scol = srow + 128;                    // [128]
        __syncthreads();
        if (tid < 128) { srow[tid] = 0.f; scol[tid] = 0.f; }
        __syncthreads();

#pragma unroll
        for (int mi = 0; mi < 4; mi++)
#pragma unroll
            for (int h = 0; h < 2; h++) {
                float rp = 0.f;
#pragma unroll
                for (int g = 0; g < 4; g++)
                    rp += acc[mi][g][2 * h + 0] + acc[mi][g][2 * h + 1];
                rp += __shfl_xor_sync(0xffffffffu, rp, 1);
                rp += __shfl_xor_sync(0xffffffffu, rp, 2);
                if ((lane & 3) == 0) {
                    int wr = wm * 64 + (lane >> 2) + mi * 16 + 8 * h;
                    atomicAdd(&srow[wr], rp);
                }
            }
#pragma unroll
        for (int g = 0; g < 4; g++)
#pragma unroll
            for (int p = 0; p < 2; p++) {
                float cp = 0.f;
#pragma unroll
                for (int mi = 0; mi < 4; mi++)
                    cp += acc[mi][g][p] + acc[mi][g][2 + p];
                cp += __shfl_xor_sync(0xffffffffu, cp, 4);
                cp += __shfl_xor_sync(0xffffffffu, cp, 8);
                cp += __shfl_xor_sync(0xffffffffu, cp, 16);
                if (lane < 4) {
                    int wc = wn * 32 + (lane & 3) * 2 + 8 * g + p;
                    atomicAdd(&scol[wc], cp);
                }
            }
        __syncthreads();
        const size_t zS = (size_t)blockIdx.z * Nn;
        if (tid < 128) {
            atomicAdd(&g_sum[zS + m0 + tid], srow[tid]);
            if (m0 != n0) atomicAdd(&g_sum[zS + n0 + tid], scol[tid]);
        }
    }
}

// ---------------- fused mirror + normalize + mask (float4) -----------------
// Each block handles a 32x128 strip of an upper-triangular 128-block (bi,bj):
// direct-normalized write of the strip, plus (bi!=bj) the transposed 128x32
// region. rinv computed inline from g_sum.
// out[r][c] = E[r][c] / sum[c] * mask[r] * mask[c]   (softmax over axis=1)
__global__ __launch_bounds__(256)
void norm_sym_kernel(float* __restrict__ S, const int* __restrict__ mask)
{
    __shared__ float sm[32][129];
    const int strip = blockIdx.x & 3;
    const int pair  = blockIdx.x >> 2;   // 0..135
    const int b     = blockIdx.y;

    int bi = 0, bj = 0, off = 0;
#pragma unroll 1
    for (int i = 0; i < 16; i++) {
        int cnt = 16 - i;
        if (pair < off + cnt) { bi = i; bj = i + pair - off; break; }
        off += cnt;
    }
    const int m0 = bi * 128 + strip * 32;   // strip rows
    const int n0 = bj * 128;                // full 128 cols
    const size_t base = (size_t)b * Nn * Nn;
    const int zS = b * Nn;

    const int t    = threadIdx.x;
    const int col4 = t & 31;                // float4 column (const across q)
    const int row0 = t >> 5;                // 0..7

    float4 sum4 = *(const float4*)(g_sum + zS + n0 + col4 * 4);
    int4   mi4  = *(const int4*)(mask + zS + n0 + col4 * 4);
    float4 c4;
    c4.x = (1.0f / sum4.x) * (float)mi4.x;
    c4.y = (1.0f / sum4.y) * (float)mi4.y;
    c4.z = (1.0f / sum4.z) * (float)mi4.z;
    c4.w = (1.0f / sum4.w) * (float)mi4.w;

#pragma unroll
    for (int q = 0; q < 4; q++) {
        const int row = row0 + 8 * q;
        const size_t go = base + (size_t)(m0 + row) * Nn + n0 + col4 * 4;
        float4 ev = *(const float4*)(S + go);
        sm[row][col4 * 4 + 0] = ev.x;
        sm[row][col4 * 4 + 1] = ev.y;
        sm[row][col4 * 4 + 2] = ev.z;
        sm[row][col4 * 4 + 3] = ev.w;
        const float mr = (float)mask[zS + m0 + row];
        float4 o;
        o.x = ev.x * c4.x * mr; o.y = ev.y * c4.y * mr;
        o.z = ev.z * c4.z * mr; o.w = ev.w * c4.w * mr;
        *(float4*)(S + go) = o;
    }
    if (bi == bj) return;                   // diag 128-block fully stored by K2

    __syncthreads();
    const int col4t = t & 7;                // const across q
    const int rbase = t >> 3;               // 0..31
    float4 sum4b = *(const float4*)(g_sum + zS + m0 + col4t * 4);
    int4   mi4b  = *(const int4*)(mask + zS + m0 + col4t * 4);
    float4 c4b;
    c4b.x = (1.0f / sum4b.x) * (float)mi4b.x;
    c4b.y = (1.0f / sum4b.y) * (float)mi4b.y;
    c4b.z = (1.0f / sum4b.z) * (float)mi4b.z;
    c4b.w = (1.0f / sum4b.w) * (float)mi4b.w;

#pragma unroll
    for (int q = 0; q < 4; q++) {
        const int rw = rbase + 32 * q;
        float4 v;
        v.x = sm[col4t * 4 + 0][rw];
        v.y = sm[col4t * 4 + 1][rw];
        v.z = sm[col4t * 4 + 2][rw];
        v.w = sm[col4t * 4 + 3][rw];
        const float mr = (float)mask[zS + n0 + rw];
        float4 o;
        o.x = v.x * c4b.x * mr; o.y = v.y * c4b.y * mr;
        o.z = v.z * c4b.z * mr; o.w = v.w * c4b.w * mr;
        *(float4*)(S + base + (size_t)(n0 + rw) * Nn + m0 + col4t * 4) = o;
    }
}

// ---------------- launch ---------------------------------------------------
extern "C" void kernel_launch(void* const* d_in, const int* in_sizes, int n_in,
                              void* d_out, int out_size)
{
    const float* ctx  = (const float*)d_in[0];   // [8, 2048, 512]
    const float* W    = (const float*)d_in[1];   // [16, 32, 512]
    const int*   mask = (const int*)d_in[2];     // [8, 2048]
    float* out = (float*)d_out;                  // [8, 2048, 2048]

    void *p_ch, *p_cl, *p_wh, *p_wl, *p_gh, *p_gl;
    cudaGetSymbolAddress(&p_ch, g_ctx_h); cudaGetSymbolAddress(&p_cl, g_ctx_l);
    cudaGetSymbolAddress(&p_wh, g_W_h);   cudaGetSymbolAddress(&p_wl, g_W_l);
    cudaGetSymbolAddress(&p_gh, g_G_h);   cudaGetSymbolAddress(&p_gl, g_G_l);
    __nv_bfloat16* Ch = (__nv_bfloat16*)p_ch; __nv_bfloat16* Cl = (__nv_bfloat16*)p_cl;
    __nv_bfloat16* Wh = (__nv_bfloat16*)p_wh; __nv_bfloat16* Wl = (__nv_bfloat16*)p_wl;
    __nv_bfloat16* Gh = (__nv_bfloat16*)p_gh; __nv_bfloat16* Gl = (__nv_bfloat16*)p_gl;

    cudaFuncSetAttribute(mma_gemm<0,1>, cudaFuncAttributeMaxDynamicSharedMemorySize, GEMM_SMEM);
    cudaFuncSetAttribute(mma_gemm<1,0>, cudaFuncAttributeMaxDynamicSharedMemorySize, GEMM_SMEM);

    // K0: split inputs into hi/lo bf16; W-split also zeroes softmax sums
    {
        int n4 = ROWS * Dd / 4;
        split_kernel<0><<<(n4 + 255) / 256, 256>>>(ctx, Ch, Cl, n4);
        int w4 = PH * Dd / 4;
        split_kernel<1><<<(w4 + 255) / 256, 256>>>(W, Wh, Wl, w4);
    }
    // K1: G = relu(ctx @ W^T) -> Gh/Gl bf16 split (fused epilogue)
    {
        dim3 grid(PH / 128, ROWS / 128, 1);
        mma_gemm<1,0><<<grid, 256, GEMM_SMEM>>>(Ch, Cl, Wh, Wl, nullptr, Gh, Gl,
                                                PH, 0, 0, 0, 1.0f);
    }
    // K2: E = exp(G·G^T/16 - 40) on upper-triangular blocks + row/col sums
    {
        dim3 grid(136, 1, Bb);
        mma_gemm<0,1><<<grid, 256, GEMM_SMEM>>>(Gh, Gl, Gh, Gl, out, nullptr, nullptr,
                                                Nn, (size_t)Nn * PH, (size_t)Nn * PH,
                                                (size_t)Nn * Nn, 1.0f / (float)Pp);
    }
    // K3: fused mirror + normalize + mask (rinv inline from g_sum)
    {
        dim3 grid(136 * 4, Bb);
        norm_sym_kernel<<<grid, 256>>>(out, mask);
    }
}

// round 16
// speedup vs baseline: 2.1283x; 1.0264x over previous
#include <cuda_runtime.h>
#include <cuda_bf16.h>
#include <stdint.h>
#include <math.h>

#define Bb 8
#define Nn 2048
#define Dd 512
#define Pp 16
#define PH 512
#define ROWS (Bb*Nn)   // 16384
#define ESHIFT 40.0f
#define LOG2E 1.44269504f

// ---------------- scratch ---------------------------------------------------
__device__ __nv_bfloat16 g_ctx_h[(size_t)ROWS * Dd];
__device__ __nv_bfloat16 g_ctx_l[(size_t)ROWS * Dd];
__device__ __nv_bfloat16 g_W_h[(size_t)PH * Dd];
__device__ __nv_bfloat16 g_W_l[(size_t)PH * Dd];
__device__ __nv_bfloat16 g_G_h[(size_t)ROWS * PH];
__device__ __nv_bfloat16 g_G_l[(size_t)ROWS * PH];
__device__ float g_sum[ROWS];    // per-row (== per-col) sum of E
__device__ int   g_ready[128];   // per-G-row-block completion counters (4 = ready)

// ---------------- small PTX helpers (base-ISA only) ------------------------
__device__ __forceinline__ uint32_t smem_u32(const void* p) {
    uint32_t a;
    asm("{ .reg .u64 t; cvta.to.shared.u64 t, %1; cvt.u32.u64 %0, t; }" : "=r"(a) : "l"(p));
    return a;
}
__device__ __forceinline__ void cpa16(uint32_t saddr, const void* g) {
    asm volatile("cp.async.cg.shared.global [%0], [%1], 16;" :: "r"(saddr), "l"(g));
}
#define CP_COMMIT() asm volatile("cp.async.commit_group;" ::: "memory")
#define CP_WAIT(n)  asm volatile("cp.async.wait_group %0;" :: "n"(n) : "memory")

__device__ __forceinline__ void ldsm4(uint32_t& d0, uint32_t& d1, uint32_t& d2, uint32_t& d3,
                                      uint32_t addr) {
    asm volatile("ldmatrix.sync.aligned.m8n8.x4.shared.b16 {%0,%1,%2,%3}, [%4];"
                 : "=r"(d0), "=r"(d1), "=r"(d2), "=r"(d3) : "r"(addr));
}
__device__ __forceinline__ void mma_bf16(float* c, const uint32_t* a, uint32_t b0, uint32_t b1) {
    asm volatile("mma.sync.aligned.m16n8k16.row.col.f32.bf16.bf16.f32 "
                 "{%0,%1,%2,%3}, {%4,%5,%6,%7}, {%8,%9}, {%0,%1,%2,%3};"
                 : "+f"(c[0]), "+f"(c[1]), "+f"(c[2]), "+f"(c[3])
                 : "r"(a[0]), "r"(a[1]), "r"(a[2]), "r"(a[3]), "r"(b0), "r"(b1));
}

// ---------------- split fp32 -> (hi, lo) bf16 ------------------------------
// ZERO=1: also zero g_sum (i < ROWS) and g_ready (i < 128).
template<int ZERO>
__global__ __launch_bounds__(256)
void split_kernel(const float* __restrict__ x, __nv_bfloat16* __restrict__ h,
                  __nv_bfloat16* __restrict__ l, int n4)
{
    int i = blockIdx.x * blockDim.x + threadIdx.x;
    if (i >= n4) return;
    if (ZERO) {
        if (i < ROWS) g_sum[i] = 0.f;
        if (i < 128)  g_ready[i] = 0;
    }
    float4 v = ((const float4*)x)[i];
    __nv_bfloat16 h0 = __float2bfloat16(v.x), h1 = __float2bfloat16(v.y);
    __nv_bfloat16 h2 = __float2bfloat16(v.z), h3 = __float2bfloat16(v.w);
    __nv_bfloat16 l0 = __float2bfloat16(v.x - __bfloat162float(h0));
    __nv_bfloat16 l1 = __float2bfloat16(v.y - __bfloat162float(h1));
    __nv_bfloat16 l2 = __float2bfloat16(v.z - __bfloat162float(h2));
    __nv_bfloat16 l3 = __float2bfloat16(v.w - __bfloat162float(h3));
    __nv_bfloat162 hp0 = __halves2bfloat162(h0, h1), hp1 = __halves2bfloat162(h2, h3);
    __nv_bfloat162 lp0 = __halves2bfloat162(l0, l1), lp1 = __halves2bfloat162(l2, l3);
    uint2 hv, lv;
    hv.x = *(uint32_t*)&hp0; hv.y = *(uint32_t*)&hp1;
    lv.x = *(uint32_t*)&lp0; lv.y = *(uint32_t*)&lp1;
    ((uint2*)h)[i] = hv;
    ((uint2*)l)[i] = lv;
}

// ---------------- persistent fused GEMM (K1 + K2) ---------------------------
// 1600 tiles: [0,512) = K1 (G = relu(ctx@W^T), split-store, sets g_ready);
//             [512,1600) = K2 (E = exp2(GG^T/16*log2e - 40*log2e), sums).
// All operand matrices have 1024-byte rows -> one mainloop, runtime pointers.
// 3 accumulation passes: Ahi·Bhi^T + Ahi·Blo^T + Alo·Bhi^T (BK=64, 3-stage).
#define ROWB    144         // 64 bf16 (128B) + 16B pad
#define NIT     24          // 3 terms * (512/64)
#define MAT_B   18432       // 128*ROWB bytes per matrix tile
#define STAGE_B (2*MAT_B)   // A + B
#define GEMM_SMEM (3*STAGE_B + 1024)
#define NTILES  1600
#define PGRID   296

__global__ __launch_bounds__(256, 2)
void fused_gemm(const __nv_bfloat16* __restrict__ ctxh, const __nv_bfloat16* __restrict__ ctxl,
                const __nv_bfloat16* __restrict__ Wh,   const __nv_bfloat16* __restrict__ Wl,
                __nv_bfloat16* __restrict__ Gh,         __nv_bfloat16* __restrict__ Gl,
                float* __restrict__ out)
{
    extern __shared__ char dsm[];

    const int tid  = threadIdx.x;
    const int wid  = tid >> 5;
    const int lane = tid & 31;
    const int wm   = wid >> 2;        // 0..1  (M warp row, 64 rows)
    const int wn   = wid & 3;         // 0..3  (N warp col, 32 cols)

    const int r0 = tid >> 3;
    const int c0 = tid & 7;
    const uint32_t s_off0 = (uint32_t)r0 * ROWB + (uint32_t)c0 * 16;

    uint32_t as_b[3], bs_b[3];
#pragma unroll
    for (int s = 0; s < 3; s++) {
        as_b[s] = smem_u32(dsm + s * STAGE_B);
        bs_b[s] = smem_u32(dsm + s * STAGE_B + MAT_B);
    }

    const int rA = wm * 64 + (lane & 15);
    const int rB = wn * 32 + (lane & 15);
    const uint32_t half16 = (uint32_t)(lane >> 4) * 16;

    for (int T = blockIdx.x; T < NTILES; T += PGRID) {
        // ---- decode tile ----
        const char *Ahb, *Alb, *Bhb, *Blb;
        int epi, m0, n0, z = 0, yrow = 0;
        if (T < 512) {
            epi  = 1;
            yrow = T >> 2;
            m0 = yrow * 128;              // global ctx row base
            n0 = (T & 3) * 128;           // W row (output col) base
            Ahb = (const char*)ctxh; Alb = (const char*)ctxl;
            Bhb = (const char*)Wh;   Blb = (const char*)Wl;
        } else {
            epi = 0;
            int T2 = T - 512;
            z = T2 / 136;
            int idx = T2 - z * 136, bi = 0, bj = 0, off = 0;
#pragma unroll 1
            for (int i = 0; i < 16; i++) {
                int cnt = 16 - i;
                if (idx < off + cnt) { bi = i; bj = i + idx - off; break; }
                off += cnt;
            }
            m0 = bi * 128; n0 = bj * 128;     // batch-local rows
            const char* Gb = (const char*)(Gh + (size_t)z * Nn * PH);
            const char* Gc = (const char*)(Gl + (size_t)z * Nn * PH);
            Ahb = Gb; Alb = Gc; Bhb = Gb; Blb = Gc;
            // wait for the two G row-blocks this tile consumes
            if (tid == 0) {
                volatile int* rf = g_ready;
                while (rf[z * 16 + bi] < 4) { }
                while (rf[z * 16 + bj] < 4) { }
            }
            __syncthreads();
            __threadfence();
        }

        const size_t a_off0 = (size_t)(m0 + r0) * 1024 + (size_t)c0 * 16;
        const size_t b_off0 = (size_t)(n0 + r0) * 1024 + (size_t)c0 * 16;

        float acc[4][4][4];
#pragma unroll
        for (int i = 0; i < 4; i++)
#pragma unroll
            for (int j = 0; j < 4; j++)
#pragma unroll
                for (int k = 0; k < 4; k++) acc[i][j][k] = 0.f;

        auto prefetch = [&](int it, int buf) {
            const int term = it >> 3;
            const int kc   = it & 7;
            const char* Ab  = (term == 2) ? Alb : Ahb;
            const char* Bbp = (term == 1) ? Blb : Bhb;
            const size_t koff = (size_t)kc * 128;
            uint32_t sa = as_b[buf] + s_off0;
            uint32_t sb = bs_b[buf] + s_off0;
#pragma unroll
            for (int q = 0; q < 4; q++) {
                cpa16(sa + q * 32 * ROWB, Ab  + a_off0 + (size_t)(q * 32) * 1024 + koff);
                cpa16(sb + q * 32 * ROWB, Bbp + b_off0 + (size_t)(q * 32) * 1024 + koff);
            }
        };

        prefetch(0, 0); CP_COMMIT();
        prefetch(1, 1); CP_COMMIT();

#pragma unroll 6
        for (int it = 0; it < NIT; ++it) {
            const int buf = it % 3;           // compile-time under unroll-6
            if (it < NIT - 1) { CP_WAIT(1); } else { CP_WAIT(0); }
            __syncthreads();

#pragma unroll
            for (int ks = 0; ks < 4; ks++) {
                uint32_t a[4][4];
                uint32_t b[2][4];
#pragma unroll
                for (int mi = 0; mi < 4; mi++) {
                    uint32_t addr = as_b[buf] + (uint32_t)(rA + mi * 16) * ROWB
                                  + (uint32_t)ks * 32 + half16;
                    ldsm4(a[mi][0], a[mi][1], a[mi][2], a[mi][3], addr);
                }
#pragma unroll
                for (int nb = 0; nb < 2; nb++) {
                    uint32_t addr = bs_b[buf] + (uint32_t)(rB + nb * 16) * ROWB
                                  + (uint32_t)ks * 32 + half16;
                    ldsm4(b[nb][0], b[nb][1], b[nb][2], b[nb][3], addr);
                }
#pragma unroll
                for (int mi = 0; mi < 4; mi++)
#pragma unroll
                    for (int g = 0; g < 4; g++)
                        mma_bf16(acc[mi][g], a[mi], b[g >> 1][g & 1], b[g >> 1][(g & 1) + 2]);
            }
            if (it + 2 < NIT) { prefetch(it + 2, (it + 2) % 3); CP_COMMIT(); }
        }

        // ---- epilogue ----
        const int er = m0 + wm * 64 + (lane >> 2);
        const int ec = n0 + wn * 32 + (lane & 3) * 2;

        if (epi == 1) {
            // relu + split-store into Gh/Gl (Ncols = 512)
#pragma unroll
            for (int mi = 0; mi < 4; mi++)
#pragma unroll
                for (int g = 0; g < 4; g++) {
                    const int r = er + mi * 16;
                    const int c = ec + g * 8;
#pragma unroll
                    for (int hrow = 0; hrow < 2; hrow++) {
                        float v0 = fmaxf(acc[mi][g][2 * hrow + 0], 0.f);
                        float v1 = fmaxf(acc[mi][g][2 * hrow + 1], 0.f);
                        __nv_bfloat16 h0 = __float2bfloat16(v0), h1 = __float2bfloat16(v1);
                        __nv_bfloat16 l0 = __float2bfloat16(v0 - __bfloat162float(h0));
                        __nv_bfloat16 l1 = __float2bfloat16(v1 - __bfloat162float(h1));
                        __nv_bfloat162 hp = __halves2bfloat162(h0, h1);
                        __nv_bfloat162 lp = __halves2bfloat162(l0, l1);
                        const size_t o = (size_t)(r + 8 * hrow) * PH + c;
                        *(uint32_t*)(Gh + o) = *(uint32_t*)&hp;
                        *(uint32_t*)(Gl + o) = *(uint32_t*)&lp;
                    }
                }
            __syncthreads();
            __threadfence();
            if (tid == 0) atomicAdd(&g_ready[yrow], 1);
        } else {
            // E = exp2(acc*a2 - s2) in-place; store to out; row/col sums
            const float a2 = (1.0f / (float)Pp) * LOG2E;
            const float s2 = ESHIFT * LOG2E;
            const size_t zC = (size_t)z * Nn * Nn;
#pragma unroll
            for (int mi = 0; mi < 4; mi++)
#pragma unroll
                for (int g = 0; g < 4; g++)
#pragma unroll
                    for (int k = 0; k < 4; k++)
                        acc[mi][g][k] = exp2f(fmaf(acc[mi][g][k], a2, -s2));

#pragma unroll
            for (int mi = 0; mi < 4; mi++)
#pragma unroll
                for (int g = 0; g < 4; g++) {
                    const int r = er + mi * 16;
                    const int c = ec + g * 8;
                    *(float2*)(out + zC + (size_t)r * Nn + c)       = make_float2(acc[mi][g][0], acc[mi][g][1]);
                    *(float2*)(out + zC + (size_t)(r + 8) * Nn + c) = make_float2(acc[mi][g][2], acc[mi][g][3]);
                }

            float* srow = (float*)(dsm + 3 * STAGE_B);   // [128]
            float* scol = srow + 128;                    // [128]
            __syncthreads();
            if (tid < 128) { srow[tid] = 0.f; scol[tid] = 0.f; }
            __syncthreads();

#pragma unroll
            for (int mi = 0; mi < 4; mi++)
#pragma unroll
                for (int h = 0; h < 2; h++) {
                    float rp = 0.f;
#pragma unroll
                    for (int g = 0; g < 4; g++)
                        rp += acc[mi][g][2 * h + 0] + acc[mi][g][2 * h + 1];
                    rp += __shfl_xor_sync(0xffffffffu, rp, 1);
                    rp += __shfl_xor_sync(0xffffffffu, rp, 2);
                    if ((lane & 3) == 0) {
                        int wr = wm * 64 + (lane >> 2) + mi * 16 + 8 * h;
                        atomicAdd(&srow[wr], rp);
                    }
                }
#pragma unroll
            for (int g = 0; g < 4; g++)
#pragma unroll
                for (int p = 0; p < 2; p++) {
                    float cp = 0.f;
#pragma unroll
                    for (int mi = 0; mi < 4; mi++)
                        cp += acc[mi][g][p] + acc[mi][g][2 + p];
                    cp += __shfl_xor_sync(0xffffffffu, cp, 4);
                    cp += __shfl_xor_sync(0xffffffffu, cp, 8);
                    cp += __shfl_xor_sync(0xffffffffu, cp, 16);
                    if (lane < 4) {
                        int wc = wn * 32 + (lane & 3) * 2 + 8 * g + p;
                        atomicAdd(&scol[wc], cp);
                    }
                }
            __syncthreads();
            const size_t zS = (size_t)z * Nn;
            if (tid < 128) {
                atomicAdd(&g_sum[zS + m0 + tid], srow[tid]);
                if (m0 != n0) atomicAdd(&g_sum[zS + n0 + tid], scol[tid]);
            }
            __syncthreads();
        }
    }
}

// ---------------- fused mirror + normalize + mask (float4) -----------------
// out[r][c] = E[r][c] / sum[c] * mask[r] * mask[c]   (softmax over axis=1)
__global__ __launch_bounds__(256)
void norm_sym_kernel(float* __restrict__ S, const int* __restrict__ mask)
{
    __shared__ float sm[32][129];
    const int strip = blockIdx.x & 3;
    const int pair  = blockIdx.x >> 2;   // 0..135
    const int b     = blockIdx.y;

    int bi = 0, bj = 0, off = 0;
#pragma unroll 1
    for (int i = 0; i < 16; i++) {
        int cnt = 16 - i;
        if (pair < off + cnt) { bi = i; bj = i + pair - off; break; }
        off += cnt;
    }
    const int m0 = bi * 128 + strip * 32;
    const int n0 = bj * 128;
    const size_t base = (size_t)b * Nn * Nn;
    const int zS = b * Nn;

    const int t    = threadIdx.x;
    const int col4 = t & 31;
    const int row0 = t >> 5;

    float4 sum4 = *(const float4*)(g_sum + zS + n0 + col4 * 4);
    int4   mi4  = *(const int4*)(mask + zS + n0 + col4 * 4);
    float4 c4;
    c4.x = (1.0f / sum4.x) * (float)mi4.x;
    c4.y = (1.0f / sum4.y) * (float)mi4.y;
    c4.z = (1.0f / sum4.z) * (float)mi4.z;
    c4.w = (1.0f / sum4.w) * (float)mi4.w;

#pragma unroll
    for (int q = 0; q < 4; q++) {
        const int row = row0 + 8 * q;
        const size_t go = base + (size_t)(m0 + row) * Nn + n0 + col4 * 4;
        float4 ev = *(const float4*)(S + go);
        sm[row][col4 * 4 + 0] = ev.x;
        sm[row][col4 * 4 + 1] = ev.y;
        sm[row][col4 * 4 + 2] = ev.z;
        sm[row][col4 * 4 + 3] = ev.w;
        const float mr = (float)mask[zS + m0 + row];
        float4 o;
        o.x = ev.x * c4.x * mr; o.y = ev.y * c4.y * mr;
        o.z = ev.z * c4.z * mr; o.w = ev.w * c4.w * mr;
        *(float4*)(S + go) = o;
    }
    if (bi == bj) return;

    __syncthreads();
    const int col4t = t & 7;
    const int rbase = t >> 3;
    float4 sum4b = *(const float4*)(g_sum + zS + m0 + col4t * 4);
    int4   mi4b  = *(const int4*)(mask + zS + m0 + col4t * 4);
    float4 c4b;
    c4b.x = (1.0f / sum4b.x) * (float)mi4b.x;
    c4b.y = (1.0f / sum4b.y) * (float)mi4b.y;
    c4b.z = (1.0f / sum4b.z) * (float)mi4b.z;
    c4b.w = (1.0f / sum4b.w) * (float)mi4b.w;

#pragma unroll
    for (int q = 0; q < 4; q++) {
        const int rw = rbase + 32 * q;
        float4 v;
        v.x = sm[col4t * 4 + 0][rw];
        v.y = sm[col4t * 4 + 1][rw];
        v.z = sm[col4t * 4 + 2][rw];
        v.w = sm[col4t * 4 + 3][rw];
        const float mr = (float)mask[zS + n0 + rw];
        float4 o;
        o.x = v.x * c4b.x * mr; o.y = v.y * c4b.y * mr;
        o.z = v.z * c4b.z * mr; o.w = v.w * c4b.w * mr;
        *(float4*)(S + base + (size_t)(n0 + rw) * Nn + m0 + col4t * 4) = o;
    }
}

// ---------------- launch ---------------------------------------------------
extern "C" void kernel_launch(void* const* d_in, const int* in_sizes, int n_in,
                              void* d_out, int out_size)
{
    const float* ctx  = (const float*)d_in[0];   // [8, 2048, 512]
    const float* W    = (const float*)d_in[1];   // [16, 32, 512]
    const int*   mask = (const int*)d_in[2];     // [8, 2048]
    float* out = (float*)d_out;                  // [8, 2048, 2048]

    void *p_ch, *p_cl, *p_wh, *p_wl, *p_gh, *p_gl;
    cudaGetSymbolAddress(&p_ch, g_ctx_h); cudaGetSymbolAddress(&p_cl, g_ctx_l);
    cudaGetSymbolAddress(&p_wh, g_W_h);   cudaGetSymbolAddress(&p_wl, g_W_l);
    cudaGetSymbolAddress(&p_gh, g_G_h);   cudaGetSymbolAddress(&p_gl, g_G_l);
    __nv_bfloat16* Ch = (__nv_bfloat16*)p_ch; __nv_bfloat16* Cl = (__nv_bfloat16*)p_cl;
    __nv_bfloat16* Wh = (__nv_bfloat16*)p_wh; __nv_bfloat16* Wl = (__nv_bfloat16*)p_wl;
    __nv_bfloat16* Gh = (__nv_bfloat16*)p_gh; __nv_bfloat16* Gl = (__nv_bfloat16*)p_gl;

    cudaFuncSetAttribute(fused_gemm, cudaFuncAttributeMaxDynamicSharedMemorySize, GEMM_SMEM);

    // K0: splits; W-split also zeroes g_sum and g_ready (stream-ordered)
    {
        int n4 = ROWS * Dd / 4;
        split_kernel<0><<<(n4 + 255) / 256, 256>>>(ctx, Ch, Cl, n4);
        int w4 = PH * Dd / 4;
        split_kernel<1><<<(w4 + 255) / 256, 256>>>(W, Wh, Wl, w4);
    }
    // K1+K2 fused persistent: projection -> ready flags -> Gram/exp/sums
    fused_gemm<<<PGRID, 256, GEMM_SMEM>>>(Ch, Cl, Wh, Wl, Gh, Gl, out);
    // K3: fused mirror + normalize + mask (rinv inline from g_sum)
    {
        dim3 grid(136 * 4, Bb);
        norm_sym_kernel<<<grid, 256>>>(out, mask);
    }
}